// round 13
// baseline (speedup 1.0000x reference)
#include <cuda_runtime.h>
#include <cuda_fp16.h>
#include <math.h>
#include <stdint.h>

#define NNODE 50000
#define NEDGE 800000
#define EPAD  (NEDGE + NNODE)
#define FDIM  256
#define NHEAD 4
#define OUTD  64
#define NBLK  ((NNODE + 1023) / 1024)   // 49 scan blocks

// ---------------- scratch ---------------------------------------------------
__device__ __align__(128) __half g_t[NNODE * FDIM];       // GEMM out, fp16 msgs
__device__ __align__(16) uint16_t g_h1h[NNODE * FDIM];    // layer-1 h, bf16 hi
__device__ __align__(16) uint16_t g_h1l[NNODE * FDIM];    // layer-1 h, bf16 lo
__device__ __align__(16) uint16_t g_h2h[NNODE * FDIM];
__device__ __align__(16) uint16_t g_h2l[NNODE * FDIM];
__device__ __align__(16) uint16_t g_w1h[FDIM * FDIM];     // W^T hi bf16 [N][K]
__device__ __align__(16) uint16_t g_w1l[FDIM * FDIM];
__device__ __align__(16) uint16_t g_w2h[FDIM * FDIM];
__device__ __align__(16) uint16_t g_w2l[FDIM * FDIM];
__device__ __align__(16) uint16_t g_wfh[OUTD * FDIM];
__device__ __align__(16) uint16_t g_wfl[OUTD * FDIM];
__device__ float g_als[NNODE * NHEAD];
__device__ float g_ald[NNODE * NHEAD];
__device__ int   g_deg[NNODE];
__device__ int   g_rowptr[NNODE + 1];
__device__ int   g_cursor[NNODE];
__device__ int   g_srcs[EPAD];
__device__ int   g_bsum[NBLK + 1];
__device__ int   g_boff[NBLK + 1];

__device__ __forceinline__ int clampi(int v, int lo, int hi) {
    return v < lo ? lo : (v > hi ? hi : v);
}
__device__ __forceinline__ uint32_t pack_bf16x2(float v0, float v1) {
    uint32_t d;
    asm("cvt.rn.bf16x2.f32 %0, %1, %2;" : "=r"(d) : "f"(v1), "f"(v0));
    return d;
}
__device__ __forceinline__ void mma_bf16(float* d, const uint32_t* a, const uint32_t* b) {
    asm volatile(
        "mma.sync.aligned.m16n8k16.row.col.f32.bf16.bf16.f32 "
        "{%0,%1,%2,%3}, {%4,%5,%6,%7}, {%8,%9}, {%0,%1,%2,%3};"
        : "+f"(d[0]), "+f"(d[1]), "+f"(d[2]), "+f"(d[3])
        : "r"(a[0]), "r"(a[1]), "r"(a[2]), "r"(a[3]), "r"(b[0]), "r"(b[1]));
}
#define LDSM_X4(r, addr)                                                     \
    asm volatile("ldmatrix.sync.aligned.m8n8.x4.shared.b16 {%0,%1,%2,%3}, [%4];" \
        : "=r"((r)[0]), "=r"((r)[1]), "=r"((r)[2]), "=r"((r)[3]) : "r"(addr))
#define CP_A16(dst, src, sz)                                                 \
    asm volatile("cp.async.cg.shared.global [%0], [%1], 16, %2;"             \
        :: "r"(dst), "l"(src), "r"(sz))
#define CP_COMMIT() asm volatile("cp.async.commit_group;" ::: "memory")
#define CP_WAIT0()  asm volatile("cp.async.wait_group 0;" ::: "memory")

// ---------------- CSR construction ------------------------------------------
__global__ void k_count_deg(const int* __restrict__ ei, int* deg) {
    int e = blockIdx.x * blockDim.x + threadIdx.x;
    if (e < NEDGE) atomicAdd(&deg[clampi(ei[NEDGE + e], 0, NNODE - 1)], 1);
}
__global__ void k_scan1(const int* __restrict__ deg, int* rowptr, int* bsum) {
    int b = blockIdx.x, tid = threadIdx.x;
    int i = b * 1024 + tid;
    int v = (i < NNODE) ? (deg[i] + 1) : 0;   // +1 self loop
    int lane = tid & 31, w = tid >> 5;
    int x = v;
#pragma unroll
    for (int off = 1; off < 32; off <<= 1) {
        int y = __shfl_up_sync(0xffffffffu, x, off);
        if (lane >= off) x += y;
    }
    __shared__ int ws[32];
    if (lane == 31) ws[w] = x;
    __syncthreads();
    if (w == 0) {
        int s = ws[lane];
#pragma unroll
        for (int off = 1; off < 32; off <<= 1) {
            int y = __shfl_up_sync(0xffffffffu, s, off);
            if (lane >= off) s += y;
        }
        ws[lane] = s;
    }
    __syncthreads();
    int wo = (w > 0) ? ws[w - 1] : 0;
    int incl = x + wo;
    if (i < NNODE) rowptr[i] = incl - v;
    if (tid == 1023) bsum[b] = incl;
}
__global__ void k_scan2(const int* __restrict__ bsum, int* boff, int* rowptr) {
    if (threadIdx.x == 0) {
        int s = 0;
        for (int b = 0; b < NBLK; b++) { boff[b] = s; s += bsum[b]; }
        rowptr[NNODE] = s;
    }
}
__global__ void k_scan3(int* rowptr, int* cursor, const int* __restrict__ boff) {
    int i = blockIdx.x * blockDim.x + threadIdx.x;
    if (i < NNODE) {
        int r = rowptr[i] + boff[i >> 10];
        rowptr[i] = r;
        cursor[i] = r;
    }
}
__global__ void k_scatter(const int* __restrict__ ei, int* cursor, int* srcs) {
    int e = blockIdx.x * blockDim.x + threadIdx.x;
    if (e < NEDGE) {
        int s = clampi(ei[e], 0, NNODE - 1);
        int d = clampi(ei[NEDGE + e], 0, NNODE - 1);
        int pos = atomicAdd(&cursor[d], 1);
        if (pos >= 0 && pos < EPAD) srcs[pos] = s;
    } else if (e < EPAD) {
        int i = e - NEDGE;
        int pos = atomicAdd(&cursor[i], 1);
        if (pos >= 0 && pos < EPAD) srcs[pos] = i;
    }
}

// ---------------- weight split/transpose: W[K][N] -> hi/lo bf16 [N][K] ------
__global__ void k_split_w(const float* __restrict__ W, uint16_t* __restrict__ WH,
                          uint16_t* __restrict__ WL, int K, int N) {
    int i = blockIdx.x * blockDim.x + threadIdx.x;
    if (i < K * N) {
        int k = i / N, n = i % N;
        float v = W[i];
        uint32_t hw = pack_bf16x2(v, 0.f);
        float hf = __uint_as_float(hw << 16);
        uint32_t lw = pack_bf16x2(v - hf, 0.f);
        WH[n * K + k] = (uint16_t)(hw & 0xffffu);
        WL[n * K + k] = (uint16_t)(lw & 0xffffu);
    }
}

// ---------------- bf16-split tensor-core GEMM + fused logits ----------------
// Double-buffered smem (1 sync per K-tile). PRESPLIT path: pure cp.async.
// GEMM1 path: A fp32 staged via regs (split in flight), B via cp.async.
template<int BN, int NOUT, bool PRESPLIT, bool HALF_C>
__global__ void __launch_bounds__(256, 2)
k_gemm_mma(const float* __restrict__ A,
           const uint16_t* __restrict__ AH, const uint16_t* __restrict__ AL,
           const uint16_t* __restrict__ BH, const uint16_t* __restrict__ BL,
           const float* __restrict__ bias, void* __restrict__ C, int M,
           const float* __restrict__ a_src, const float* __restrict__ a_dst,
           float* __restrict__ als_out, float* __restrict__ ald_out) {
    constexpr int RS = 40;                 // smem row stride (halves)
    constexpr int WN = BN / 2;
    constexpr int NT = WN / 8;
    constexpr int NP = NT / 2;
    constexpr int ABYTES = 128 * RS * 2;   // 10240
    constexpr int BBYTES = BN * RS * 2;
    constexpr int AOFF_H = 0, AOFF_L = ABYTES;
    constexpr int BOFF_H = 2 * ABYTES, BOFF_L = 2 * ABYTES + BBYTES;
    constexpr int STAGE = 2 * ABYTES + 2 * BBYTES;
    constexpr int B_CH = BN / 64;          // 16B chunks per thread per B array

    extern __shared__ __align__(16) char smem[];
    const uint32_t sb = (uint32_t)__cvta_generic_to_shared(smem);

    const int tid  = threadIdx.x;
    const int wid  = tid >> 5, lane = tid & 31;
    const int wm   = wid & 3, wn = wid >> 2;
    const int g    = lane >> 2, tq = lane & 3;
    const int brow = blockIdx.x * 128;
    const int bcol = blockIdx.y * BN;

    float acc[2][NT][4];
#pragma unroll
    for (int mt = 0; mt < 2; mt++)
#pragma unroll
        for (int nt = 0; nt < NT; nt++)
#pragma unroll
            for (int r = 0; r < 4; r++) acc[mt][nt][r] = 0.f;

    // per-lane ldmatrix byte offsets (within each array)
    const int lane8 = lane & 7, lh = (lane >> 3) & 1, lq = lane >> 4;
    uint32_t aOff[2], bOff[NP];
#pragma unroll
    for (int mt = 0; mt < 2; mt++) {
        int ar = wm * 32 + mt * 16 + lane8 + lh * 8;
        aOff[mt] = (uint32_t)(ar * RS + lq * 8) * 2;
    }
#pragma unroll
    for (int p = 0; p < NP; p++) {
        int br = wn * WN + p * 16 + lane8 + lq * 8;
        bOff[p] = (uint32_t)(br * RS + lh * 8) * 2;
    }

    // cp.async issue of B (always) into given stage
    auto cpB = [&](int k0, int stage) {
        uint32_t sbase = sb + stage * STAGE;
#pragma unroll
        for (int u = 0; u < B_CH; u++) {
            int q = tid + u * 256;
            int row = q >> 2, c8 = q & 3;
            size_t gi = (size_t)(bcol + row) * 256 + k0 + c8 * 8;
            uint32_t d = sbase + (uint32_t)(row * (RS * 2) + c8 * 16);
            CP_A16(d + BOFF_H, BH + gi, 16);
            CP_A16(d + BOFF_L, BL + gi, 16);
        }
    };
    // cp.async issue of A (PRESPLIT only)
    auto cpA = [&](int k0, int stage) {
        uint32_t sbase = sb + stage * STAGE;
#pragma unroll
        for (int u = 0; u < 2; u++) {
            int q = tid + u * 256;
            int row = q >> 2, c8 = q & 3;
            int gr = brow + row;
            int sz = (gr < M) ? 16 : 0;
            int grc = (gr < M) ? gr : 0;
            size_t gi = (size_t)grc * 256 + k0 + c8 * 8;
            uint32_t d = sbase + (uint32_t)(row * (RS * 2) + c8 * 16);
            CP_A16(d + AOFF_H, AH + gi, sz);
            CP_A16(d + AOFF_L, AL + gi, sz);
        }
    };

    // register staging for fp32 A (GEMM1 path)
    float4 aS[4];
    auto loadA = [&](int k0) {
#pragma unroll
        for (int u = 0; u < 4; u++) {
            int q = tid + u * 256;
            int row = q >> 3, f4 = q & 7;
            int gr = brow + row;
            aS[u] = make_float4(0.f, 0.f, 0.f, 0.f);
            if (gr < M) aS[u] = *reinterpret_cast<const float4*>(&A[(size_t)gr * 256 + k0 + f4 * 4]);
        }
    };
    auto storeA = [&](int stage) {
        uint16_t* pAh = reinterpret_cast<uint16_t*>(smem + stage * STAGE + AOFF_H);
        uint16_t* pAl = reinterpret_cast<uint16_t*>(smem + stage * STAGE + AOFF_L);
#pragma unroll
        for (int u = 0; u < 4; u++) {
            int q = tid + u * 256;
            int row = q >> 3, f4 = q & 7;
            int idx = row * RS + f4 * 4;
            float v[4] = {aS[u].x, aS[u].y, aS[u].z, aS[u].w};
#pragma unroll
            for (int h2i = 0; h2i < 2; h2i++) {
                uint32_t hw = pack_bf16x2(v[h2i * 2], v[h2i * 2 + 1]);
                float f0 = __uint_as_float(hw << 16);
                float f1 = __uint_as_float(hw & 0xffff0000u);
                uint32_t lw = pack_bf16x2(v[h2i * 2] - f0, v[h2i * 2 + 1] - f1);
                *reinterpret_cast<uint32_t*>(pAh + idx + h2i * 2) = hw;
                *reinterpret_cast<uint32_t*>(pAl + idx + h2i * 2) = lw;
            }
        }
    };

    auto compute = [&](int stage) {
        uint32_t sbase = sb + stage * STAGE;
#pragma unroll
        for (int ks = 0; ks < 2; ks++) {
            const uint32_t kb = ks * 32;
            uint32_t ah[2][4], al[2][4];
            LDSM_X4(ah[0], sbase + AOFF_H + aOff[0] + kb);
            LDSM_X4(ah[1], sbase + AOFF_H + aOff[1] + kb);
            LDSM_X4(al[0], sbase + AOFF_L + aOff[0] + kb);
            LDSM_X4(al[1], sbase + AOFF_L + aOff[1] + kb);
#pragma unroll
            for (int p = 0; p < NP; p++) {
                uint32_t bh[4], bl[4];
                LDSM_X4(bh, sbase + BOFF_H + bOff[p] + kb);
                LDSM_X4(bl, sbase + BOFF_L + bOff[p] + kb);
#pragma unroll
                for (int mt = 0; mt < 2; mt++) {
                    mma_bf16(acc[mt][2 * p],     ah[mt], bh);
                    mma_bf16(acc[mt][2 * p],     ah[mt], bl);
                    mma_bf16(acc[mt][2 * p],     al[mt], bh);
                    mma_bf16(acc[mt][2 * p + 1], ah[mt], bh + 2);
                    mma_bf16(acc[mt][2 * p + 1], ah[mt], bl + 2);
                    mma_bf16(acc[mt][2 * p + 1], al[mt], bh + 2);
                }
            }
        }
    };

    // ---- pipelined mainloop (8 K-tiles of 32), 2 smem stages, 1 sync/tile --
    if (PRESPLIT) {
        cpA(0, 0); cpB(0, 0); CP_COMMIT();
        CP_WAIT0(); __syncthreads();
        int buf = 0;
        for (int t = 0; t < 8; t++) {
            if (t < 7) { cpA((t + 1) * 32, buf ^ 1); cpB((t + 1) * 32, buf ^ 1); CP_COMMIT(); }
            compute(buf);
            if (t < 7) { CP_WAIT0(); __syncthreads(); buf ^= 1; }
        }
    } else {
        cpB(0, 0); CP_COMMIT();
        loadA(0); storeA(0);
        CP_WAIT0(); __syncthreads();
        int buf = 0;
        for (int t = 0; t < 8; t++) {
            if (t < 7) { cpB((t + 1) * 32, buf ^ 1); CP_COMMIT(); loadA((t + 1) * 32); }
            compute(buf);
            if (t < 7) { storeA(buf ^ 1); CP_WAIT0(); __syncthreads(); buf ^= 1; }
        }
    }

    // epilogue
#pragma unroll
    for (int mt = 0; mt < 2; mt++) {
        int r0 = brow + wm * 32 + mt * 16 + g;
        int r1 = r0 + 8;
#pragma unroll
        for (int nt = 0; nt < NT; nt++) {
            int col = bcol + wn * WN + nt * 8 + tq * 2;
            if (HALF_C) {
                __half2* Ch = reinterpret_cast<__half2*>(C);
                if (r0 < M)
                    Ch[(size_t)r0 * (NOUT / 2) + col / 2] =
                        __floats2half2_rn(acc[mt][nt][0], acc[mt][nt][1]);
                if (r1 < M)
                    Ch[(size_t)r1 * (NOUT / 2) + col / 2] =
                        __floats2half2_rn(acc[mt][nt][2], acc[mt][nt][3]);
            } else {
                float* Cf = reinterpret_cast<float*>(C);
                float b0 = 0.f, b1 = 0.f;
                if (bias) { b0 = bias[col]; b1 = bias[col + 1]; }
                if (r0 < M)
                    *reinterpret_cast<float2*>(&Cf[(size_t)r0 * NOUT + col]) =
                        make_float2(acc[mt][nt][0] + b0, acc[mt][nt][1] + b1);
                if (r1 < M)
                    *reinterpret_cast<float2*>(&Cf[(size_t)r1 * NOUT + col]) =
                        make_float2(acc[mt][nt][2] + b0, acc[mt][nt][3] + b1);
            }
        }
    }

    // fused attention logits (BN==128): head = blockIdx.y*2 + wn (fp32 acc)
    if (als_out) {
        int head = blockIdx.y * 2 + wn;
#pragma unroll
        for (int mt = 0; mt < 2; mt++) {
#pragma unroll
            for (int half = 0; half < 2; half++) {
                float ps = 0.f, pd = 0.f;
#pragma unroll
                for (int nt = 0; nt < NT; nt++) {
                    int col = bcol + wn * WN + nt * 8 + tq * 2;
                    float a0 = acc[mt][nt][half * 2 + 0];
                    float a1 = acc[mt][nt][half * 2 + 1];
                    ps += a0 * a_src[col] + a1 * a_src[col + 1];
                    pd += a0 * a_dst[col] + a1 * a_dst[col + 1];
                }
                ps += __shfl_xor_sync(0xffffffffu, ps, 1);
                pd += __shfl_xor_sync(0xffffffffu, pd, 1);
                ps += __shfl_xor_sync(0xffffffffu, ps, 2);
                pd += __shfl_xor_sync(0xffffffffu, pd, 2);
                int row = brow + wm * 32 + mt * 16 + g + half * 8;
                if (tq == 0 && row < M) {
                    als_out[row * NHEAD + head] = ps;
                    ald_out[row * NHEAD + head] = pd;
                }
            }
        }
    }
}

// ---------------- warp-synchronous aggregation, 4-edge ILP ------------------
// One node per 128-thread block; warp w owns head w.
// lane = eg*8 + cl: edge-group eg in 0..3 (4 edges in flight), channel-slice
// cl in 0..7 (16B = 4 half2 per lane). LDG.128 gathers; eg-partials folded
// by shfl_xor(8,16) at the end.
__global__ void __launch_bounds__(128)
k_gat_aggregate(const uint4* __restrict__ h4,    // fp16 msg table, 32 uint4/row
                const int* __restrict__ rowptr,
                const int* __restrict__ srcs,
                const float* __restrict__ als,
                const float* __restrict__ ald,
                const float* __restrict__ bias,
                uint16_t* __restrict__ outh, uint16_t* __restrict__ outl) {
    int n = blockIdx.x;
    int w = threadIdx.x >> 5;    // head == warp
    int lane = threadIdx.x & 31;
    int eg = lane >> 3;          // edge group 0..3
    int cl = lane & 7;           // channel slice 0..7

    int p0  = rowptr[n];
    int deg = rowptr[n + 1] - p0;

    float aldv = __ldg(&ald[n * NHEAD + w]);
    float accf[8];
#pragma unroll
    for (int k = 0; k < 8; k++) accf[k] = 0.f;
    float dsum = 0.f;

    for (int base = 0; base < deg; base += 32) {
        int j = base + lane;
        int s = 0;
        float wt = 0.f;
        if (j < deg) {
            s = srcs[p0 + j];
            float e = als[s * NHEAD + w] + aldv;
            e = (e > 0.f) ? e : 0.2f * e;
            wt = __expf(e);
            dsum += wt;
        }
        int lim = min(32, deg - base);
        int steps = (lim + 3) >> 2;
#pragma unroll 2
        for (int j2 = 0; j2 < steps; j2++) {
            int sl = j2 * 4 + eg;
            int   ss = __shfl_sync(0xffffffffu, s,  sl);
            float ww = __shfl_sync(0xffffffffu, wt, sl);   // 0 for tail-invalid
            uint4 v = h4[(size_t)ss * 32 + w * 8 + cl];
            float2 f0 = __half22float2(*reinterpret_cast<__half2*>(&v.x));
            float2 f1 = __half22float2(*reinterpret_cast<__half2*>(&v.y));
            float2 f2 = __half22float2(*reinterpret_cast<__half2*>(&v.z));
            float2 f3 = __half22float2(*reinterpret_cast<__half2*>(&v.w));
            accf[0] += ww * f0.x; accf[1] += ww * f0.y;
            accf[2] += ww * f1.x; accf[3] += ww * f1.y;
            accf[4] += ww * f2.x; accf[5] += ww * f2.y;
            accf[6] += ww * f3.x; accf[7] += ww * f3.y;
        }
    }

    // fold the 4 edge-group partials (lanes differing in bits 3,4 share channels)
#pragma unroll
    for (int k = 0; k < 8; k++) {
        accf[k] += __shfl_xor_sync(0xffffffffu, accf[k], 8);
        accf[k] += __shfl_xor_sync(0xffffffffu, accf[k], 16);
    }
#pragma unroll
    for (int off = 16; off >= 1; off >>= 1)
        dsum += __shfl_xor_sync(0xffffffffu, dsum, off);

    if (eg == 0) {
        float inv = 1.f / dsum;
        const float* bp = &bias[w * 64 + cl * 8];
        uint32_t hi4[4], lo4[4];
#pragma unroll
        for (int k = 0; k < 4; k++) {
            float o0 = accf[2 * k]     * inv + bp[2 * k];
            float o1 = accf[2 * k + 1] * inv + bp[2 * k + 1];
            o0 = (o0 > 0.f) ? o0 : expm1f(o0);
            o1 = (o1 > 0.f) ? o1 : expm1f(o1);
            uint32_t hw = pack_bf16x2(o0, o1);
            float f0 = __uint_as_float(hw << 16);
            float f1 = __uint_as_float(hw & 0xffff0000u);
            hi4[k] = hw;
            lo4[k] = pack_bf16x2(o0 - f0, o1 - f1);
        }
        size_t oi = (size_t)n * 32 + w * 8 + cl;   // uint4 index (16B units)
        reinterpret_cast<uint4*>(outh)[oi] = make_uint4(hi4[0], hi4[1], hi4[2], hi4[3]);
        reinterpret_cast<uint4*>(outl)[oi] = make_uint4(lo4[0], lo4[1], lo4[2], lo4[3]);
    }
}

// ---------------- launch ----------------------------------------------------
extern "C" void kernel_launch(void* const* d_in, const int* in_sizes, int n_in,
                              void* d_out, int out_size) {
    const float* x     = (const float*)d_in[0];
    const int*   ei    = (const int*)d_in[1];   // int32 (JAX x64 disabled)
    const float* W1    = (const float*)d_in[3];
    const float* asrc1 = (const float*)d_in[4];
    const float* adst1 = (const float*)d_in[5];
    const float* b1    = (const float*)d_in[6];
    const float* W2    = (const float*)d_in[7];
    const float* asrc2 = (const float*)d_in[8];
    const float* adst2 = (const float*)d_in[9];
    const float* b2    = (const float*)d_in[10];
    const float* fcW   = (const float*)d_in[11];
    const float* fcb   = (const float*)d_in[12];
    float* out = (float*)d_out;

    __half* t;
    float *als, *ald;
    uint16_t *h1h, *h1l, *h2h, *h2l;
    uint16_t *w1h, *w1l, *w2h, *w2l, *wfh, *wfl;
    int *deg, *rowptr, *cursor, *srcs, *bsum, *boff;
    cudaGetSymbolAddress((void**)&t, g_t);
    cudaGetSymbolAddress((void**)&h1h, g_h1h);
    cudaGetSymbolAddress((void**)&h1l, g_h1l);
    cudaGetSymbolAddress((void**)&h2h, g_h2h);
    cudaGetSymbolAddress((void**)&h2l, g_h2l);
    cudaGetSymbolAddress((void**)&als, g_als);
    cudaGetSymbolAddress((void**)&ald, g_ald);
    cudaGetSymbolAddress((void**)&w1h, g_w1h);
    cudaGetSymbolAddress((void**)&w1l, g_w1l);
    cudaGetSymbolAddress((void**)&w2h, g_w2h);
    cudaGetSymbolAddress((void**)&w2l, g_w2l);
    cudaGetSymbolAddress((void**)&wfh, g_wfh);
    cudaGetSymbolAddress((void**)&wfl, g_wfl);
    cudaGetSymbolAddress((void**)&deg, g_deg);
    cudaGetSymbolAddress((void**)&rowptr, g_rowptr);
    cudaGetSymbolAddress((void**)&cursor, g_cursor);
    cudaGetSymbolAddress((void**)&srcs, g_srcs);
    cudaGetSymbolAddress((void**)&bsum, g_bsum);
    cudaGetSymbolAddress((void**)&boff, g_boff);

    constexpr int SMEM_BIG = 2 * (2 * 10240 + 2 * 10240);   // 81920
    constexpr int SMEM_FC  = 2 * (2 * 10240 + 2 * 5120);    // 61440

    // one-time init (first call = correctness run, outside graph capture)
    static cudaStream_t s2 = nullptr;
    static cudaEvent_t evFork = nullptr, evJoin = nullptr;
    if (s2 == nullptr) {
        cudaStreamCreateWithFlags(&s2, cudaStreamNonBlocking);
        cudaEventCreateWithFlags(&evFork, cudaEventDisableTiming);
        cudaEventCreateWithFlags(&evJoin, cudaEventDisableTiming);
        cudaFuncSetAttribute((const void*)k_gemm_mma<128, 256, false, true>,
                             cudaFuncAttributeMaxDynamicSharedMemorySize, SMEM_BIG);
        cudaFuncSetAttribute((const void*)k_gemm_mma<128, 256, true, true>,
                             cudaFuncAttributeMaxDynamicSharedMemorySize, SMEM_BIG);
        cudaFuncSetAttribute((const void*)k_gemm_mma<64, 64, true, false>,
                             cudaFuncAttributeMaxDynamicSharedMemorySize, SMEM_FC);
    }

    const int NTILE = (NNODE + 127) / 128;   // 391
    dim3 gbig(NTILE, 2);
    dim3 gfc(NTILE, 1);

    // fork side stream
    cudaEventRecord(evFork, 0);
    cudaStreamWaitEvent(s2, evFork, 0);

    // main #1 (overall #3 after 2 harness kernels)
    k_split_w<<<(FDIM * FDIM + 255) / 256, 256>>>(W1, w1h, w1l, FDIM, FDIM);
    cudaMemsetAsync(deg, 0, NNODE * sizeof(int), s2);
    k_count_deg<<<(NEDGE + 255) / 256, 256, 0, s2>>>(ei, deg);
    k_scan1<<<NBLK, 1024, 0, s2>>>(deg, rowptr, bsum);

    // overall #6: layer-1 GEMM (profiled by ncu -s 5 -c 1)
    k_gemm_mma<128, 256, false, true><<<gbig, 256, SMEM_BIG>>>(
        x, nullptr, nullptr, w1h, w1l, nullptr, t, NNODE, asrc1, adst1, als, ald);

    // rest of CSR + weight splits on side stream
    k_scan2<<<1, 32, 0, s2>>>(bsum, boff, rowptr);
    k_scan3<<<NBLK, 1024, 0, s2>>>(rowptr, cursor, boff);
    k_scatter<<<(EPAD + 255) / 256, 256, 0, s2>>>(ei, cursor, srcs);
    k_split_w<<<(FDIM * FDIM + 255) / 256, 256, 0, s2>>>(W2, w2h, w2l, FDIM, FDIM);
    k_split_w<<<(FDIM * OUTD + 255) / 256, 256, 0, s2>>>(fcW, wfh, wfl, FDIM, OUTD);
    cudaEventRecord(evJoin, s2);

    // join: aggregation needs CSR; layer-2 GEMM needs W2 split
    cudaStreamWaitEvent(0, evJoin, 0);

    // layer 1 aggregate -> h1 (bf16 split); one node per block
    k_gat_aggregate<<<NNODE, 128>>>((const uint4*)t, rowptr, srcs, als, ald,
                                    b1, h1h, h1l);

    // layer 2
    k_gemm_mma<128, 256, true, true><<<gbig, 256, SMEM_BIG>>>(
        nullptr, h1h, h1l, w2h, w2l, nullptr, t, NNODE, asrc2, adst2, als, ald);
    k_gat_aggregate<<<NNODE, 128>>>((const uint4*)t, rowptr, srcs, als, ald,
                                    b2, h2h, h2l);

    // fc head (fp32 out + bias)
    k_gemm_mma<64, 64, true, false><<<gfc, 256, SMEM_FC>>>(
        nullptr, h2h, h2l, wfh, wfl, fcb, out, NNODE,
        nullptr, nullptr, nullptr, nullptr);
}

// round 14
// speedup vs baseline: 1.2354x; 1.2354x over previous
#include <cuda_runtime.h>
#include <cuda_fp16.h>
#include <math.h>
#include <stdint.h>

#define NNODE 50000
#define NEDGE 800000
#define EPAD  (NEDGE + NNODE)
#define FDIM  256
#define NHEAD 4
#define OUTD  64
#define NBLK  ((NNODE + 1023) / 1024)   // 49 scan blocks

// ---------------- scratch ---------------------------------------------------
__device__ __align__(128) __half g_t[NNODE * FDIM];       // GEMM out, fp16 msgs
__device__ __align__(16) __half g_h1[NNODE * FDIM];       // layer-1 h, fp16
__device__ __align__(16) __half g_h2[NNODE * FDIM];       // layer-2 h, fp16
__device__ __align__(16) uint16_t g_w1h[FDIM * FDIM];     // W1^T hi bf16 [N][K]
__device__ __align__(16) uint16_t g_w1l[FDIM * FDIM];     // W1^T lo bf16
__device__ __align__(16) uint16_t g_w2h[FDIM * FDIM];     // W2^T hi fp16
__device__ __align__(16) uint16_t g_w2l[FDIM * FDIM];     // W2^T lo fp16
__device__ __align__(16) uint16_t g_wfh[OUTD * FDIM];     // fcW^T hi fp16
__device__ __align__(16) uint16_t g_wfl[OUTD * FDIM];     // fcW^T lo fp16
__device__ float g_als[NNODE * NHEAD];
__device__ float g_ald[NNODE * NHEAD];
__device__ int   g_deg[NNODE];
__device__ int   g_rowptr[NNODE + 1];
__device__ int   g_cursor[NNODE];
__device__ int   g_srcs[EPAD];
__device__ int   g_bsum[NBLK + 1];
__device__ int   g_boff[NBLK + 1];

__device__ __forceinline__ int clampi(int v, int lo, int hi) {
    return v < lo ? lo : (v > hi ? hi : v);
}
__device__ __forceinline__ uint32_t pack_bf16x2(float v0, float v1) {
    uint32_t d;
    asm("cvt.rn.bf16x2.f32 %0, %1, %2;" : "=r"(d) : "f"(v1), "f"(v0));
    return d;
}
__device__ __forceinline__ void mma_bf16(float* d, const uint32_t* a, const uint32_t* b) {
    asm volatile(
        "mma.sync.aligned.m16n8k16.row.col.f32.bf16.bf16.f32 "
        "{%0,%1,%2,%3}, {%4,%5,%6,%7}, {%8,%9}, {%0,%1,%2,%3};"
        : "+f"(d[0]), "+f"(d[1]), "+f"(d[2]), "+f"(d[3])
        : "r"(a[0]), "r"(a[1]), "r"(a[2]), "r"(a[3]), "r"(b[0]), "r"(b[1]));
}
__device__ __forceinline__ void mma_f16(float* d, const uint32_t* a, const uint32_t* b) {
    asm volatile(
        "mma.sync.aligned.m16n8k16.row.col.f32.f16.f16.f32 "
        "{%0,%1,%2,%3}, {%4,%5,%6,%7}, {%8,%9}, {%0,%1,%2,%3};"
        : "+f"(d[0]), "+f"(d[1]), "+f"(d[2]), "+f"(d[3])
        : "r"(a[0]), "r"(a[1]), "r"(a[2]), "r"(a[3]), "r"(b[0]), "r"(b[1]));
}
#define LDSM_X4(r, addr)                                                     \
    asm volatile("ldmatrix.sync.aligned.m8n8.x4.shared.b16 {%0,%1,%2,%3}, [%4];" \
        : "=r"((r)[0]), "=r"((r)[1]), "=r"((r)[2]), "=r"((r)[3]) : "r"(addr))
#define CP_A16(dst, src, sz)                                                 \
    asm volatile("cp.async.cg.shared.global [%0], [%1], 16, %2;"             \
        :: "r"(dst), "l"(src), "r"(sz))
#define CP_COMMIT() asm volatile("cp.async.commit_group;" ::: "memory")
#define CP_WAIT0()  asm volatile("cp.async.wait_group 0;" ::: "memory")

// ---------------- CSR construction ------------------------------------------
__global__ void k_count_deg(const int* __restrict__ ei, int* deg) {
    int e = blockIdx.x * blockDim.x + threadIdx.x;
    if (e < NEDGE) atomicAdd(&deg[clampi(ei[NEDGE + e], 0, NNODE - 1)], 1);
}
__global__ void k_scan1(const int* __restrict__ deg, int* rowptr, int* bsum) {
    int b = blockIdx.x, tid = threadIdx.x;
    int i = b * 1024 + tid;
    int v = (i < NNODE) ? (deg[i] + 1) : 0;   // +1 self loop
    int lane = tid & 31, w = tid >> 5;
    int x = v;
#pragma unroll
    for (int off = 1; off < 32; off <<= 1) {
        int y = __shfl_up_sync(0xffffffffu, x, off);
        if (lane >= off) x += y;
    }
    __shared__ int ws[32];
    if (lane == 31) ws[w] = x;
    __syncthreads();
    if (w == 0) {
        int s = ws[lane];
#pragma unroll
        for (int off = 1; off < 32; off <<= 1) {
            int y = __shfl_up_sync(0xffffffffu, s, off);
            if (lane >= off) s += y;
        }
        ws[lane] = s;
    }
    __syncthreads();
    int wo = (w > 0) ? ws[w - 1] : 0;
    int incl = x + wo;
    if (i < NNODE) rowptr[i] = incl - v;
    if (tid == 1023) bsum[b] = incl;
}
__global__ void k_scan2(const int* __restrict__ bsum, int* boff, int* rowptr) {
    if (threadIdx.x == 0) {
        int s = 0;
        for (int b = 0; b < NBLK; b++) { boff[b] = s; s += bsum[b]; }
        rowptr[NNODE] = s;
    }
}
__global__ void k_scan3(int* rowptr, int* cursor, const int* __restrict__ boff) {
    int i = blockIdx.x * blockDim.x + threadIdx.x;
    if (i < NNODE) {
        int r = rowptr[i] + boff[i >> 10];
        rowptr[i] = r;
        cursor[i] = r;
    }
}
__global__ void k_scatter(const int* __restrict__ ei, int* cursor, int* srcs) {
    int e = blockIdx.x * blockDim.x + threadIdx.x;
    if (e < NEDGE) {
        int s = clampi(ei[e], 0, NNODE - 1);
        int d = clampi(ei[NEDGE + e], 0, NNODE - 1);
        int pos = atomicAdd(&cursor[d], 1);
        if (pos >= 0 && pos < EPAD) srcs[pos] = s;
    } else if (e < EPAD) {
        int i = e - NEDGE;
        int pos = atomicAdd(&cursor[i], 1);
        if (pos >= 0 && pos < EPAD) srcs[pos] = i;
    }
}

// ---------------- weight splits: W[K][N] -> hi/lo [N][K] --------------------
__global__ void k_split_w_bf16(const float* __restrict__ W, uint16_t* __restrict__ WH,
                               uint16_t* __restrict__ WL, int K, int N) {
    int i = blockIdx.x * blockDim.x + threadIdx.x;
    if (i < K * N) {
        int k = i / N, n = i % N;
        float v = W[i];
        uint32_t hw = pack_bf16x2(v, 0.f);
        float hf = __uint_as_float(hw << 16);
        uint32_t lw = pack_bf16x2(v - hf, 0.f);
        WH[n * K + k] = (uint16_t)(hw & 0xffffu);
        WL[n * K + k] = (uint16_t)(lw & 0xffffu);
    }
}
__global__ void k_split_w_f16(const float* __restrict__ W, uint16_t* __restrict__ WH,
                              uint16_t* __restrict__ WL, int K, int N) {
    int i = blockIdx.x * blockDim.x + threadIdx.x;
    if (i < K * N) {
        int k = i / N, n = i % N;
        float v = W[i];
        __half h = __float2half_rn(v);
        __half l = __float2half_rn(v - __half2float(h));
        WH[n * K + k] = __half_as_ushort(h);
        WL[n * K + k] = __half_as_ushort(l);
    }
}

// ---------------- tensor-core GEMM + fused logits ---------------------------
// MODE 0: A fp32 (split to bf16 hi/lo in-kernel), B bf16 hi/lo, 3-term.
// MODE 1: A fp16 presplit (single array AH), B fp16 hi/lo, 2-term.
// Double-buffered smem, cp.async B (and A in MODE1), 1 sync per K-tile.
template<int BN, int NOUT, int MODE, bool HALF_C>
__global__ void __launch_bounds__(256, 2)
k_gemm_mma(const float* __restrict__ A,
           const uint16_t* __restrict__ AH,
           const uint16_t* __restrict__ BH, const uint16_t* __restrict__ BL,
           const float* __restrict__ bias, void* __restrict__ C, int M,
           const float* __restrict__ a_src, const float* __restrict__ a_dst,
           float* __restrict__ als_out, float* __restrict__ ald_out) {
    constexpr int RS = 40;                 // smem row stride (halves)
    constexpr int WN = BN / 2;
    constexpr int NT = WN / 8;
    constexpr int NP = NT / 2;
    constexpr int ABYTES = 128 * RS * 2;   // 10240
    constexpr int BBYTES = BN * RS * 2;
    constexpr int AOFF_H = 0;
    constexpr int AOFF_L = ABYTES;                       // MODE0 only
    constexpr int B_BASE = (MODE == 0) ? 2 * ABYTES : ABYTES;
    constexpr int BOFF_H = B_BASE;
    constexpr int BOFF_L = B_BASE + BBYTES;
    constexpr int STAGE  = B_BASE + 2 * BBYTES;
    constexpr int B_CH = BN / 64;          // 16B chunks/thread per B array

    extern __shared__ __align__(16) char smem[];
    const uint32_t sb = (uint32_t)__cvta_generic_to_shared(smem);

    const int tid  = threadIdx.x;
    const int wid  = tid >> 5, lane = tid & 31;
    const int wm   = wid & 3, wn = wid >> 2;
    const int g    = lane >> 2, tq = lane & 3;
    const int brow = blockIdx.x * 128;
    const int bcol = blockIdx.y * BN;

    float acc[2][NT][4];
#pragma unroll
    for (int mt = 0; mt < 2; mt++)
#pragma unroll
        for (int nt = 0; nt < NT; nt++)
#pragma unroll
            for (int r = 0; r < 4; r++) acc[mt][nt][r] = 0.f;

    // per-lane ldmatrix byte offsets (within each array)
    const int lane8 = lane & 7, lh = (lane >> 3) & 1, lq = lane >> 4;
    uint32_t aOff[2], bOff[NP];
#pragma unroll
    for (int mt = 0; mt < 2; mt++) {
        int ar = wm * 32 + mt * 16 + lane8 + lh * 8;
        aOff[mt] = (uint32_t)(ar * RS + lq * 8) * 2;
    }
#pragma unroll
    for (int p = 0; p < NP; p++) {
        int br = wn * WN + p * 16 + lane8 + lq * 8;
        bOff[p] = (uint32_t)(br * RS + lh * 8) * 2;
    }

    auto cpB = [&](int k0, int stage) {
        uint32_t sbase = sb + stage * STAGE;
#pragma unroll
        for (int u = 0; u < B_CH; u++) {
            int q = tid + u * 256;
            int row = q >> 2, c8 = q & 3;
            size_t gi = (size_t)(bcol + row) * 256 + k0 + c8 * 8;
            uint32_t d = sbase + (uint32_t)(row * (RS * 2) + c8 * 16);
            CP_A16(d + BOFF_H, BH + gi, 16);
            CP_A16(d + BOFF_L, BL + gi, 16);
        }
    };
    // cp.async A (MODE1 only; single fp16 array)
    auto cpA = [&](int k0, int stage) {
        uint32_t sbase = sb + stage * STAGE;
#pragma unroll
        for (int u = 0; u < 2; u++) {
            int q = tid + u * 256;
            int row = q >> 2, c8 = q & 3;
            int gr = brow + row;
            int sz = (gr < M) ? 16 : 0;
            int grc = (gr < M) ? gr : 0;
            size_t gi = (size_t)grc * 256 + k0 + c8 * 8;
            uint32_t d = sbase + (uint32_t)(row * (RS * 2) + c8 * 16);
            CP_A16(d + AOFF_H, AH + gi, sz);
        }
    };

    // register staging for fp32 A (MODE0)
    float4 aS[4];
    auto loadA = [&](int k0) {
#pragma unroll
        for (int u = 0; u < 4; u++) {
            int q = tid + u * 256;
            int row = q >> 3, f4 = q & 7;
            int gr = brow + row;
            aS[u] = make_float4(0.f, 0.f, 0.f, 0.f);
            if (gr < M) aS[u] = *reinterpret_cast<const float4*>(&A[(size_t)gr * 256 + k0 + f4 * 4]);
        }
    };
    auto storeA = [&](int stage) {
        uint16_t* pAh = reinterpret_cast<uint16_t*>(smem + stage * STAGE + AOFF_H);
        uint16_t* pAl = reinterpret_cast<uint16_t*>(smem + stage * STAGE + AOFF_L);
#pragma unroll
        for (int u = 0; u < 4; u++) {
            int q = tid + u * 256;
            int row = q >> 3, f4 = q & 7;
            int idx = row * RS + f4 * 4;
            float v[4] = {aS[u].x, aS[u].y, aS[u].z, aS[u].w};
#pragma unroll
            for (int h2i = 0; h2i < 2; h2i++) {
                uint32_t hw = pack_bf16x2(v[h2i * 2], v[h2i * 2 + 1]);
                float f0 = __uint_as_float(hw << 16);
                float f1 = __uint_as_float(hw & 0xffff0000u);
                uint32_t lw = pack_bf16x2(v[h2i * 2] - f0, v[h2i * 2 + 1] - f1);
                *reinterpret_cast<uint32_t*>(pAh + idx + h2i * 2) = hw;
                *reinterpret_cast<uint32_t*>(pAl + idx + h2i * 2) = lw;
            }
        }
    };

    auto compute = [&](int stage) {
        uint32_t sbase = sb + stage * STAGE;
#pragma unroll
        for (int ks = 0; ks < 2; ks++) {
            const uint32_t kb = ks * 32;
            uint32_t ah[2][4], al[2][4];
            LDSM_X4(ah[0], sbase + AOFF_H + aOff[0] + kb);
            LDSM_X4(ah[1], sbase + AOFF_H + aOff[1] + kb);
            if (MODE == 0) {
                LDSM_X4(al[0], sbase + AOFF_L + aOff[0] + kb);
                LDSM_X4(al[1], sbase + AOFF_L + aOff[1] + kb);
            }
#pragma unroll
            for (int p = 0; p < NP; p++) {
                uint32_t bh[4], bl[4];
                LDSM_X4(bh, sbase + BOFF_H + bOff[p] + kb);
                LDSM_X4(bl, sbase + BOFF_L + bOff[p] + kb);
#pragma unroll
                for (int mt = 0; mt < 2; mt++) {
                    if (MODE == 0) {
                        mma_bf16(acc[mt][2 * p],     ah[mt], bh);
                        mma_bf16(acc[mt][2 * p],     ah[mt], bl);
                        mma_bf16(acc[mt][2 * p],     al[mt], bh);
                        mma_bf16(acc[mt][2 * p + 1], ah[mt], bh + 2);
                        mma_bf16(acc[mt][2 * p + 1], ah[mt], bl + 2);
                        mma_bf16(acc[mt][2 * p + 1], al[mt], bh + 2);
                    } else {
                        mma_f16(acc[mt][2 * p],     ah[mt], bh);
                        mma_f16(acc[mt][2 * p],     ah[mt], bl);
                        mma_f16(acc[mt][2 * p + 1], ah[mt], bh + 2);
                        mma_f16(acc[mt][2 * p + 1], ah[mt], bl + 2);
                    }
                }
            }
        }
    };

    // ---- pipelined mainloop (8 K-tiles of 32), 2 smem stages, 1 sync/tile --
    if (MODE == 1) {
        cpA(0, 0); cpB(0, 0); CP_COMMIT();
        CP_WAIT0(); __syncthreads();
        int buf = 0;
        for (int t = 0; t < 8; t++) {
            if (t < 7) { cpA((t + 1) * 32, buf ^ 1); cpB((t + 1) * 32, buf ^ 1); CP_COMMIT(); }
            compute(buf);
            if (t < 7) { CP_WAIT0(); __syncthreads(); buf ^= 1; }
        }
    } else {
        cpB(0, 0); CP_COMMIT();
        loadA(0); storeA(0);
        CP_WAIT0(); __syncthreads();
        int buf = 0;
        for (int t = 0; t < 8; t++) {
            if (t < 7) { cpB((t + 1) * 32, buf ^ 1); CP_COMMIT(); loadA((t + 1) * 32); }
            compute(buf);
            if (t < 7) { storeA(buf ^ 1); CP_WAIT0(); __syncthreads(); buf ^= 1; }
        }
    }

    // epilogue
#pragma unroll
    for (int mt = 0; mt < 2; mt++) {
        int r0 = brow + wm * 32 + mt * 16 + g;
        int r1 = r0 + 8;
#pragma unroll
        for (int nt = 0; nt < NT; nt++) {
            int col = bcol + wn * WN + nt * 8 + tq * 2;
            if (HALF_C) {
                __half2* Ch = reinterpret_cast<__half2*>(C);
                if (r0 < M)
                    Ch[(size_t)r0 * (NOUT / 2) + col / 2] =
                        __floats2half2_rn(acc[mt][nt][0], acc[mt][nt][1]);
                if (r1 < M)
                    Ch[(size_t)r1 * (NOUT / 2) + col / 2] =
                        __floats2half2_rn(acc[mt][nt][2], acc[mt][nt][3]);
            } else {
                float* Cf = reinterpret_cast<float*>(C);
                float b0 = 0.f, b1 = 0.f;
                if (bias) { b0 = bias[col]; b1 = bias[col + 1]; }
                if (r0 < M)
                    *reinterpret_cast<float2*>(&Cf[(size_t)r0 * NOUT + col]) =
                        make_float2(acc[mt][nt][0] + b0, acc[mt][nt][1] + b1);
                if (r1 < M)
                    *reinterpret_cast<float2*>(&Cf[(size_t)r1 * NOUT + col]) =
                        make_float2(acc[mt][nt][2] + b0, acc[mt][nt][3] + b1);
            }
        }
    }

    // fused attention logits (BN==128): head = blockIdx.y*2 + wn (fp32 acc)
    if (als_out) {
        int head = blockIdx.y * 2 + wn;
#pragma unroll
        for (int mt = 0; mt < 2; mt++) {
#pragma unroll
            for (int half = 0; half < 2; half++) {
                float ps = 0.f, pd = 0.f;
#pragma unroll
                for (int nt = 0; nt < NT; nt++) {
                    int col = bcol + wn * WN + nt * 8 + tq * 2;
                    float a0 = acc[mt][nt][half * 2 + 0];
                    float a1 = acc[mt][nt][half * 2 + 1];
                    ps += a0 * a_src[col] + a1 * a_src[col + 1];
                    pd += a0 * a_dst[col] + a1 * a_dst[col + 1];
                }
                ps += __shfl_xor_sync(0xffffffffu, ps, 1);
                pd += __shfl_xor_sync(0xffffffffu, pd, 1);
                ps += __shfl_xor_sync(0xffffffffu, ps, 2);
                pd += __shfl_xor_sync(0xffffffffu, pd, 2);
                int row = brow + wm * 32 + mt * 16 + g + half * 8;
                if (tq == 0 && row < M) {
                    als_out[row * NHEAD + head] = ps;
                    ald_out[row * NHEAD + head] = pd;
                }
            }
        }
    }
}

// ---------------- warp-synchronous aggregation (fp16 msgs, fp16 out) --------
// One node per 128-thread block; warp w owns head w (32 half2 channels).
__global__ void __launch_bounds__(128)
k_gat_aggregate(const __half2* __restrict__ hsrc,
                const int* __restrict__ rowptr,
                const int* __restrict__ srcs,
                const float* __restrict__ als,
                const float* __restrict__ ald,
                const float* __restrict__ bias,
                __half2* __restrict__ outv) {
    int n = blockIdx.x;
    int w = threadIdx.x >> 5;    // head == warp
    int lane = threadIdx.x & 31;
    int c2 = w * 32 + lane;

    int p0  = rowptr[n];
    int deg = rowptr[n + 1] - p0;

    float aldv = __ldg(&ald[n * NHEAD + w]);
    float accx = 0.f, accy = 0.f, dsum = 0.f;

    for (int base = 0; base < deg; base += 32) {
        int j = base + lane;
        int s = 0;
        float wt = 0.f;
        if (j < deg) {
            s = srcs[p0 + j];
            float e = als[s * NHEAD + w] + aldv;
            e = (e > 0.f) ? e : 0.2f * e;
            wt = __expf(e);
            dsum += wt;
        }
        int lim = min(32, deg - base);
#pragma unroll 4
        for (int j2 = 0; j2 < lim; j2++) {
            int   ss = __shfl_sync(0xffffffffu, s,  j2);
            float ww = __shfl_sync(0xffffffffu, wt, j2);
            float2 v = __half22float2(hsrc[(size_t)ss * 128 + c2]);
            accx += ww * v.x;
            accy += ww * v.y;
        }
    }

#pragma unroll
    for (int off = 16; off >= 1; off >>= 1)
        dsum += __shfl_xor_sync(0xffffffffu, dsum, off);

    float inv = 1.f / dsum;
    float o0 = accx * inv + bias[2 * c2];
    float o1 = accy * inv + bias[2 * c2 + 1];
    o0 = (o0 > 0.f) ? o0 : expm1f(o0);
    o1 = (o1 > 0.f) ? o1 : expm1f(o1);

    outv[(size_t)n * 128 + c2] = __floats2half2_rn(o0, o1);
}

// ---------------- launch ----------------------------------------------------
extern "C" void kernel_launch(void* const* d_in, const int* in_sizes, int n_in,
                              void* d_out, int out_size) {
    const float* x     = (const float*)d_in[0];
    const int*   ei    = (const int*)d_in[1];   // int32 (JAX x64 disabled)
    const float* W1    = (const float*)d_in[3];
    const float* asrc1 = (const float*)d_in[4];
    const float* adst1 = (const float*)d_in[5];
    const float* b1    = (const float*)d_in[6];
    const float* W2    = (const float*)d_in[7];
    const float* asrc2 = (const float*)d_in[8];
    const float* adst2 = (const float*)d_in[9];
    const float* b2    = (const float*)d_in[10];
    const float* fcW   = (const float*)d_in[11];
    const float* fcb   = (const float*)d_in[12];
    float* out = (float*)d_out;

    __half *t, *h1, *h2;
    float *als, *ald;
    uint16_t *w1h, *w1l, *w2h, *w2l, *wfh, *wfl;
    int *deg, *rowptr, *cursor, *srcs, *bsum, *boff;
    cudaGetSymbolAddress((void**)&t, g_t);
    cudaGetSymbolAddress((void**)&h1, g_h1);
    cudaGetSymbolAddress((void**)&h2, g_h2);
    cudaGetSymbolAddress((void**)&als, g_als);
    cudaGetSymbolAddress((void**)&ald, g_ald);
    cudaGetSymbolAddress((void**)&w1h, g_w1h);
    cudaGetSymbolAddress((void**)&w1l, g_w1l);
    cudaGetSymbolAddress((void**)&w2h, g_w2h);
    cudaGetSymbolAddress((void**)&w2l, g_w2l);
    cudaGetSymbolAddress((void**)&wfh, g_wfh);
    cudaGetSymbolAddress((void**)&wfl, g_wfl);
    cudaGetSymbolAddress((void**)&deg, g_deg);
    cudaGetSymbolAddress((void**)&rowptr, g_rowptr);
    cudaGetSymbolAddress((void**)&cursor, g_cursor);
    cudaGetSymbolAddress((void**)&srcs, g_srcs);
    cudaGetSymbolAddress((void**)&bsum, g_bsum);
    cudaGetSymbolAddress((void**)&boff, g_boff);

    constexpr int SMEM_G1 = 2 * (2 * 10240 + 2 * 10240);   // 81920 (MODE0 big)
    constexpr int SMEM_G2 = 2 * (10240 + 2 * 10240);       // 61440 (MODE1 big)
    constexpr int SMEM_FC = 2 * (10240 + 2 * 5120);        // 40960 (MODE1 fc)

    // one-time init (first call = correctness run, outside graph capture)
    static cudaStream_t s2 = nullptr;
    static cudaEvent_t evFork = nullptr, evJoin = nullptr;
    if (s2 == nullptr) {
        cudaStreamCreateWithFlags(&s2, cudaStreamNonBlocking);
        cudaEventCreateWithFlags(&evFork, cudaEventDisableTiming);
        cudaEventCreateWithFlags(&evJoin, cudaEventDisableTiming);
        cudaFuncSetAttribute((const void*)k_gemm_mma<128, 256, 0, true>,
                             cudaFuncAttributeMaxDynamicSharedMemorySize, SMEM_G1);
        cudaFuncSetAttribute((const void*)k_gemm_mma<128, 256, 1, true>,
                             cudaFuncAttributeMaxDynamicSharedMemorySize, SMEM_G2);
        cudaFuncSetAttribute((const void*)k_gemm_mma<64, 64, 1, false>,
                             cudaFuncAttributeMaxDynamicSharedMemorySize, SMEM_FC);
    }

    const int NTILE = (NNODE + 127) / 128;   // 391
    dim3 gbig(NTILE, 2);
    dim3 gfc(NTILE, 1);

    // fork side stream
    cudaEventRecord(evFork, 0);
    cudaStreamWaitEvent(s2, evFork, 0);

    // main #1 (overall #3 after 2 harness kernels)
    k_split_w_bf16<<<(FDIM * FDIM + 255) / 256, 256>>>(W1, w1h, w1l, FDIM, FDIM);
    cudaMemsetAsync(deg, 0, NNODE * sizeof(int), s2);
    k_count_deg<<<(NEDGE + 255) / 256, 256, 0, s2>>>(ei, deg);
    k_scan1<<<NBLK, 1024, 0, s2>>>(deg, rowptr, bsum);

    // overall #6: layer-1 GEMM (profiled by ncu -s 5 -c 1)
    k_gemm_mma<128, 256, 0, true><<<gbig, 256, SMEM_G1>>>(
        x, nullptr, w1h, w1l, nullptr, t, NNODE, asrc1, adst1, als, ald);

    // rest of CSR + weight splits on side stream
    k_scan2<<<1, 32, 0, s2>>>(bsum, boff, rowptr);
    k_scan3<<<NBLK, 1024, 0, s2>>>(rowptr, cursor, boff);
    k_scatter<<<(EPAD + 255) / 256, 256, 0, s2>>>(ei, cursor, srcs);
    k_split_w_f16<<<(FDIM * FDIM + 255) / 256, 256, 0, s2>>>(W2, w2h, w2l, FDIM, FDIM);
    k_split_w_f16<<<(FDIM * OUTD + 255) / 256, 256, 0, s2>>>(fcW, wfh, wfl, FDIM, OUTD);
    cudaEventRecord(evJoin, s2);

    // join: aggregation needs CSR; layer-2 GEMM needs W2 split
    cudaStreamWaitEvent(0, evJoin, 0);

    // layer 1 aggregate -> h1 (fp16)
    k_gat_aggregate<<<NNODE, 128>>>((const __half2*)t, rowptr, srcs, als, ald,
                                    b1, (__half2*)h1);

    // layer 2 (fp16 2-term)
    k_gemm_mma<128, 256, 1, true><<<gbig, 256, SMEM_G2>>>(
        nullptr, (const uint16_t*)h1, w2h, w2l, nullptr, t, NNODE,
        asrc2, adst2, als, ald);
    k_gat_aggregate<<<NNODE, 128>>>((const __half2*)t, rowptr, srcs, als, ald,
                                    b2, (__half2*)h2);

    // fc head (fp16 2-term, fp32 out + bias)
    k_gemm_mma<64, 64, 1, false><<<gfc, 256, SMEM_FC>>>(
        nullptr, (const uint16_t*)h2, wfh, wfl, fcb, out, NNODE,
        nullptr, nullptr, nullptr, nullptr);
}

// round 15
// speedup vs baseline: 1.2389x; 1.0028x over previous
#include <cuda_runtime.h>
#include <cuda_fp16.h>
#include <math.h>
#include <stdint.h>

#define NNODE 50000
#define NEDGE 800000
#define EPAD  (NEDGE + NNODE)
#define FDIM  256
#define NHEAD 4
#define OUTD  64
#define NBLK  ((NNODE + 1023) / 1024)   // 49 scan blocks

// ---------------- scratch ---------------------------------------------------
__device__ __align__(128) __half g_t[NNODE * FDIM];       // GEMM out, fp16 msgs
__device__ __align__(16) __half g_xh[NNODE * FDIM];       // x as fp16
__device__ __align__(16) __half g_h1[NNODE * FDIM];       // layer-1 h, fp16
__device__ __align__(16) __half g_h2[NNODE * FDIM];       // layer-2 h, fp16
__device__ __align__(16) uint16_t g_w1h[FDIM * FDIM];     // W1^T hi fp16 [N][K]
__device__ __align__(16) uint16_t g_w1l[FDIM * FDIM];
__device__ __align__(16) uint16_t g_w2h[FDIM * FDIM];
__device__ __align__(16) uint16_t g_w2l[FDIM * FDIM];
__device__ __align__(16) uint16_t g_wfh[OUTD * FDIM];
__device__ __align__(16) uint16_t g_wfl[OUTD * FDIM];
__device__ float g_als[NNODE * NHEAD];
__device__ float g_ald[NNODE * NHEAD];
__device__ int   g_deg[NNODE];
__device__ int   g_rowptr[NNODE + 1];
__device__ int   g_cursor[NNODE];
__device__ int   g_srcs[EPAD];
__device__ int   g_bsum[NBLK + 1];
__device__ int   g_boff[NBLK + 1];

__device__ __forceinline__ int clampi(int v, int lo, int hi) {
    return v < lo ? lo : (v > hi ? hi : v);
}
__device__ __forceinline__ void mma_f16(float* d, const uint32_t* a, const uint32_t* b) {
    asm volatile(
        "mma.sync.aligned.m16n8k16.row.col.f32.f16.f16.f32 "
        "{%0,%1,%2,%3}, {%4,%5,%6,%7}, {%8,%9}, {%0,%1,%2,%3};"
        : "+f"(d[0]), "+f"(d[1]), "+f"(d[2]), "+f"(d[3])
        : "r"(a[0]), "r"(a[1]), "r"(a[2]), "r"(a[3]), "r"(b[0]), "r"(b[1]));
}
#define LDSM_X4(r, addr)                                                     \
    asm volatile("ldmatrix.sync.aligned.m8n8.x4.shared.b16 {%0,%1,%2,%3}, [%4];" \
        : "=r"((r)[0]), "=r"((r)[1]), "=r"((r)[2]), "=r"((r)[3]) : "r"(addr))
#define CP_A16(dst, src, sz)                                                 \
    asm volatile("cp.async.cg.shared.global [%0], [%1], 16, %2;"             \
        :: "r"(dst), "l"(src), "r"(sz))
#define CP_COMMIT() asm volatile("cp.async.commit_group;" ::: "memory")
#define CP_WAIT0()  asm volatile("cp.async.wait_group 0;" ::: "memory")

// ---------------- CSR construction ------------------------------------------
__global__ void k_count_deg(const int* __restrict__ ei, int* deg) {
    int e = blockIdx.x * blockDim.x + threadIdx.x;
    if (e < NEDGE) atomicAdd(&deg[clampi(ei[NEDGE + e], 0, NNODE - 1)], 1);
}
__global__ void k_scan1(const int* __restrict__ deg, int* rowptr, int* bsum) {
    int b = blockIdx.x, tid = threadIdx.x;
    int i = b * 1024 + tid;
    int v = (i < NNODE) ? (deg[i] + 1) : 0;   // +1 self loop
    int lane = tid & 31, w = tid >> 5;
    int x = v;
#pragma unroll
    for (int off = 1; off < 32; off <<= 1) {
        int y = __shfl_up_sync(0xffffffffu, x, off);
        if (lane >= off) x += y;
    }
    __shared__ int ws[32];
    if (lane == 31) ws[w] = x;
    __syncthreads();
    if (w == 0) {
        int s = ws[lane];
#pragma unroll
        for (int off = 1; off < 32; off <<= 1) {
            int y = __shfl_up_sync(0xffffffffu, s, off);
            if (lane >= off) s += y;
        }
        ws[lane] = s;
    }
    __syncthreads();
    int wo = (w > 0) ? ws[w - 1] : 0;
    int incl = x + wo;
    if (i < NNODE) rowptr[i] = incl - v;
    if (tid == 1023) bsum[b] = incl;
}
__global__ void k_scan2(const int* __restrict__ bsum, int* boff, int* rowptr) {
    if (threadIdx.x == 0) {
        int s = 0;
        for (int b = 0; b < NBLK; b++) { boff[b] = s; s += bsum[b]; }
        rowptr[NNODE] = s;
    }
}
__global__ void k_scan3(int* rowptr, int* cursor, const int* __restrict__ boff) {
    int i = blockIdx.x * blockDim.x + threadIdx.x;
    if (i < NNODE) {
        int r = rowptr[i] + boff[i >> 10];
        rowptr[i] = r;
        cursor[i] = r;
    }
}
__global__ void k_scatter(const int* __restrict__ ei, int* cursor, int* srcs) {
    int e = blockIdx.x * blockDim.x + threadIdx.x;
    if (e < NEDGE) {
        int s = clampi(ei[e], 0, NNODE - 1);
        int d = clampi(ei[NEDGE + e], 0, NNODE - 1);
        int pos = atomicAdd(&cursor[d], 1);
        if (pos >= 0 && pos < EPAD) srcs[pos] = s;
    } else if (e < EPAD) {
        int i = e - NEDGE;
        int pos = atomicAdd(&cursor[i], 1);
        if (pos >= 0 && pos < EPAD) srcs[pos] = i;
    }
}

// ---------------- conversions ------------------------------------------------
// x fp32 -> fp16 (same [N][256] layout), vectorized 4-at-a-time
__global__ void k_cvt_x(const float4* __restrict__ X, __half2* __restrict__ XH) {
    int i = blockIdx.x * blockDim.x + threadIdx.x;   // float4 index
    if (i < NNODE * FDIM / 4) {
        float4 v = X[i];
        XH[2 * i]     = __floats2half2_rn(v.x, v.y);
        XH[2 * i + 1] = __floats2half2_rn(v.z, v.w);
    }
}
// W[K][N] -> fp16 hi/lo [N][K]
__global__ void k_split_w_f16(const float* __restrict__ W, uint16_t* __restrict__ WH,
                              uint16_t* __restrict__ WL, int K, int N) {
    int i = blockIdx.x * blockDim.x + threadIdx.x;
    if (i < K * N) {
        int k = i / N, n = i % N;
        float v = W[i];
        __half h = __float2half_rn(v);
        __half l = __float2half_rn(v - __half2float(h));
        WH[n * K + k] = __half_as_ushort(h);
        WL[n * K + k] = __half_as_ushort(l);
    }
}

// ---------------- fp16 2-term tensor-core GEMM + fused logits ---------------
// A fp16 presplit [M][256]; B fp16 hi/lo [NOUT][256] K-major. 2 MMAs/tile.
// Double-buffered smem via cp.async, 1 sync per K-tile.
template<int BN, int NOUT, bool HALF_C>
__global__ void __launch_bounds__(256, 2)
k_gemm_mma(const uint16_t* __restrict__ AH,
           const uint16_t* __restrict__ BH, const uint16_t* __restrict__ BL,
           const float* __restrict__ bias, void* __restrict__ C, int M,
           const float* __restrict__ a_src, const float* __restrict__ a_dst,
           float* __restrict__ als_out, float* __restrict__ ald_out) {
    constexpr int RS = 40;                 // smem row stride (halves)
    constexpr int WN = BN / 2;
    constexpr int NT = WN / 8;
    constexpr int NP = NT / 2;
    constexpr int ABYTES = 128 * RS * 2;   // 10240
    constexpr int BBYTES = BN * RS * 2;
    constexpr int AOFF_H = 0;
    constexpr int BOFF_H = ABYTES;
    constexpr int BOFF_L = ABYTES + BBYTES;
    constexpr int STAGE  = ABYTES + 2 * BBYTES;
    constexpr int B_CH = BN / 64;          // 16B chunks/thread per B array

    extern __shared__ __align__(16) char smem[];
    const uint32_t sb = (uint32_t)__cvta_generic_to_shared(smem);

    const int tid  = threadIdx.x;
    const int wid  = tid >> 5, lane = tid & 31;
    const int wm   = wid & 3, wn = wid >> 2;
    const int g    = lane >> 2, tq = lane & 3;
    const int brow = blockIdx.x * 128;
    const int bcol = blockIdx.y * BN;

    float acc[2][NT][4];
#pragma unroll
    for (int mt = 0; mt < 2; mt++)
#pragma unroll
        for (int nt = 0; nt < NT; nt++)
#pragma unroll
            for (int r = 0; r < 4; r++) acc[mt][nt][r] = 0.f;

    const int lane8 = lane & 7, lh = (lane >> 3) & 1, lq = lane >> 4;
    uint32_t aOff[2], bOff[NP];
#pragma unroll
    for (int mt = 0; mt < 2; mt++) {
        int ar = wm * 32 + mt * 16 + lane8 + lh * 8;
        aOff[mt] = (uint32_t)(ar * RS + lq * 8) * 2;
    }
#pragma unroll
    for (int p = 0; p < NP; p++) {
        int br = wn * WN + p * 16 + lane8 + lq * 8;
        bOff[p] = (uint32_t)(br * RS + lh * 8) * 2;
    }

    auto cpB = [&](int k0, int stage) {
        uint32_t sbase = sb + stage * STAGE;
#pragma unroll
        for (int u = 0; u < B_CH; u++) {
            int q = tid + u * 256;
            int row = q >> 2, c8 = q & 3;
            size_t gi = (size_t)(bcol + row) * 256 + k0 + c8 * 8;
            uint32_t d = sbase + (uint32_t)(row * (RS * 2) + c8 * 16);
            CP_A16(d + BOFF_H, BH + gi, 16);
            CP_A16(d + BOFF_L, BL + gi, 16);
        }
    };
    auto cpA = [&](int k0, int stage) {
        uint32_t sbase = sb + stage * STAGE;
#pragma unroll
        for (int u = 0; u < 2; u++) {
            int q = tid + u * 256;
            int row = q >> 2, c8 = q & 3;
            int gr = brow + row;
            int sz = (gr < M) ? 16 : 0;
            int grc = (gr < M) ? gr : 0;
            size_t gi = (size_t)grc * 256 + k0 + c8 * 8;
            uint32_t d = sbase + (uint32_t)(row * (RS * 2) + c8 * 16);
            CP_A16(d + AOFF_H, AH + gi, sz);
        }
    };

    auto compute = [&](int stage) {
        uint32_t sbase = sb + stage * STAGE;
#pragma unroll
        for (int ks = 0; ks < 2; ks++) {
            const uint32_t kb = ks * 32;
            uint32_t ah[2][4];
            LDSM_X4(ah[0], sbase + AOFF_H + aOff[0] + kb);
            LDSM_X4(ah[1], sbase + AOFF_H + aOff[1] + kb);
#pragma unroll
            for (int p = 0; p < NP; p++) {
                uint32_t bh[4], bl[4];
                LDSM_X4(bh, sbase + BOFF_H + bOff[p] + kb);
                LDSM_X4(bl, sbase + BOFF_L + bOff[p] + kb);
#pragma unroll
                for (int mt = 0; mt < 2; mt++) {
                    mma_f16(acc[mt][2 * p],     ah[mt], bh);
                    mma_f16(acc[mt][2 * p],     ah[mt], bl);
                    mma_f16(acc[mt][2 * p + 1], ah[mt], bh + 2);
                    mma_f16(acc[mt][2 * p + 1], ah[mt], bl + 2);
                }
            }
        }
    };

    cpA(0, 0); cpB(0, 0); CP_COMMIT();
    CP_WAIT0(); __syncthreads();
    int buf = 0;
    for (int t = 0; t < 8; t++) {
        if (t < 7) { cpA((t + 1) * 32, buf ^ 1); cpB((t + 1) * 32, buf ^ 1); CP_COMMIT(); }
        compute(buf);
        if (t < 7) { CP_WAIT0(); __syncthreads(); buf ^= 1; }
    }

    // epilogue
#pragma unroll
    for (int mt = 0; mt < 2; mt++) {
        int r0 = brow + wm * 32 + mt * 16 + g;
        int r1 = r0 + 8;
#pragma unroll
        for (int nt = 0; nt < NT; nt++) {
            int col = bcol + wn * WN + nt * 8 + tq * 2;
            if (HALF_C) {
                __half2* Ch = reinterpret_cast<__half2*>(C);
                if (r0 < M)
                    Ch[(size_t)r0 * (NOUT / 2) + col / 2] =
                        __floats2half2_rn(acc[mt][nt][0], acc[mt][nt][1]);
                if (r1 < M)
                    Ch[(size_t)r1 * (NOUT / 2) + col / 2] =
                        __floats2half2_rn(acc[mt][nt][2], acc[mt][nt][3]);
            } else {
                float* Cf = reinterpret_cast<float*>(C);
                float b0 = 0.f, b1 = 0.f;
                if (bias) { b0 = bias[col]; b1 = bias[col + 1]; }
                if (r0 < M)
                    *reinterpret_cast<float2*>(&Cf[(size_t)r0 * NOUT + col]) =
                        make_float2(acc[mt][nt][0] + b0, acc[mt][nt][1] + b1);
                if (r1 < M)
                    *reinterpret_cast<float2*>(&Cf[(size_t)r1 * NOUT + col]) =
                        make_float2(acc[mt][nt][2] + b0, acc[mt][nt][3] + b1);
            }
        }
    }

    // fused attention logits (BN==128): head = blockIdx.y*2 + wn (fp32 acc)
    if (als_out) {
        int head = blockIdx.y * 2 + wn;
#pragma unroll
        for (int mt = 0; mt < 2; mt++) {
#pragma unroll
            for (int half = 0; half < 2; half++) {
                float ps = 0.f, pd = 0.f;
#pragma unroll
                for (int nt = 0; nt < NT; nt++) {
                    int col = bcol + wn * WN + nt * 8 + tq * 2;
                    float a0 = acc[mt][nt][half * 2 + 0];
                    float a1 = acc[mt][nt][half * 2 + 1];
                    ps += a0 * a_src[col] + a1 * a_src[col + 1];
                    pd += a0 * a_dst[col] + a1 * a_dst[col + 1];
                }
                ps += __shfl_xor_sync(0xffffffffu, ps, 1);
                pd += __shfl_xor_sync(0xffffffffu, pd, 1);
                ps += __shfl_xor_sync(0xffffffffu, ps, 2);
                pd += __shfl_xor_sync(0xffffffffu, pd, 2);
                int row = brow + wm * 32 + mt * 16 + g + half * 8;
                if (tq == 0 && row < M) {
                    als_out[row * NHEAD + head] = ps;
                    ald_out[row * NHEAD + head] = pd;
                }
            }
        }
    }
}

// ---------------- warp-synchronous aggregation (fp16 msgs, fp16 out) --------
// One node per 128-thread block; warp w owns head w (32 half2 channels).
// 2 edges per inner step with independent accumulator pairs (chain break).
__global__ void __launch_bounds__(128)
k_gat_aggregate(const __half2* __restrict__ hsrc,
                const int* __restrict__ rowptr,
                const int* __restrict__ srcs,
                const float* __restrict__ als,
                const float* __restrict__ ald,
                const float* __restrict__ bias,
                __half2* __restrict__ outv) {
    int n = blockIdx.x;
    int w = threadIdx.x >> 5;    // head == warp
    int lane = threadIdx.x & 31;
    int c2 = w * 32 + lane;

    int p0  = rowptr[n];
    int deg = rowptr[n + 1] - p0;

    float aldv = __ldg(&ald[n * NHEAD + w]);
    float ax0 = 0.f, ay0 = 0.f, ax1 = 0.f, ay1 = 0.f, dsum = 0.f;

    for (int base = 0; base < deg; base += 32) {
        int j = base + lane;
        int s = 0;
        float wt = 0.f;
        if (j < deg) {
            s = srcs[p0 + j];
            float e = als[s * NHEAD + w] + aldv;
            e = (e > 0.f) ? e : 0.2f * e;
            wt = __expf(e);
            dsum += wt;
        }
        int lim = min(32, deg - base);
        int j2 = 0;
#pragma unroll 2
        for (; j2 + 1 < lim; j2 += 2) {
            int   s0 = __shfl_sync(0xffffffffu, s,  j2);
            float w0 = __shfl_sync(0xffffffffu, wt, j2);
            int   s1 = __shfl_sync(0xffffffffu, s,  j2 + 1);
            float w1 = __shfl_sync(0xffffffffu, wt, j2 + 1);
            float2 v0 = __half22float2(hsrc[(size_t)s0 * 128 + c2]);
            float2 v1 = __half22float2(hsrc[(size_t)s1 * 128 + c2]);
            ax0 += w0 * v0.x; ay0 += w0 * v0.y;
            ax1 += w1 * v1.x; ay1 += w1 * v1.y;
        }
        if (j2 < lim) {
            int   s0 = __shfl_sync(0xffffffffu, s,  j2);
            float w0 = __shfl_sync(0xffffffffu, wt, j2);
            float2 v0 = __half22float2(hsrc[(size_t)s0 * 128 + c2]);
            ax0 += w0 * v0.x; ay0 += w0 * v0.y;
        }
    }

    float accx = ax0 + ax1, accy = ay0 + ay1;
#pragma unroll
    for (int off = 16; off >= 1; off >>= 1)
        dsum += __shfl_xor_sync(0xffffffffu, dsum, off);

    float inv = 1.f / dsum;
    float o0 = accx * inv + bias[2 * c2];
    float o1 = accy * inv + bias[2 * c2 + 1];
    o0 = (o0 > 0.f) ? o0 : expm1f(o0);
    o1 = (o1 > 0.f) ? o1 : expm1f(o1);

    outv[(size_t)n * 128 + c2] = __floats2half2_rn(o0, o1);
}

// ---------------- launch ----------------------------------------------------
extern "C" void kernel_launch(void* const* d_in, const int* in_sizes, int n_in,
                              void* d_out, int out_size) {
    const float* x     = (const float*)d_in[0];
    const int*   ei    = (const int*)d_in[1];   // int32 (JAX x64 disabled)
    const float* W1    = (const float*)d_in[3];
    const float* asrc1 = (const float*)d_in[4];
    const float* adst1 = (const float*)d_in[5];
    const float* b1    = (const float*)d_in[6];
    const float* W2    = (const float*)d_in[7];
    const float* asrc2 = (const float*)d_in[8];
    const float* adst2 = (const float*)d_in[9];
    const float* b2    = (const float*)d_in[10];
    const float* fcW   = (const float*)d_in[11];
    const float* fcb   = (const float*)d_in[12];
    float* out = (float*)d_out;

    __half *t, *xh, *h1, *h2;
    float *als, *ald;
    uint16_t *w1h, *w1l, *w2h, *w2l, *wfh, *wfl;
    int *deg, *rowptr, *cursor, *srcs, *bsum, *boff;
    cudaGetSymbolAddress((void**)&t, g_t);
    cudaGetSymbolAddress((void**)&xh, g_xh);
    cudaGetSymbolAddress((void**)&h1, g_h1);
    cudaGetSymbolAddress((void**)&h2, g_h2);
    cudaGetSymbolAddress((void**)&als, g_als);
    cudaGetSymbolAddress((void**)&ald, g_ald);
    cudaGetSymbolAddress((void**)&w1h, g_w1h);
    cudaGetSymbolAddress((void**)&w1l, g_w1l);
    cudaGetSymbolAddress((void**)&w2h, g_w2h);
    cudaGetSymbolAddress((void**)&w2l, g_w2l);
    cudaGetSymbolAddress((void**)&wfh, g_wfh);
    cudaGetSymbolAddress((void**)&wfl, g_wfl);
    cudaGetSymbolAddress((void**)&deg, g_deg);
    cudaGetSymbolAddress((void**)&rowptr, g_rowptr);
    cudaGetSymbolAddress((void**)&cursor, g_cursor);
    cudaGetSymbolAddress((void**)&srcs, g_srcs);
    cudaGetSymbolAddress((void**)&bsum, g_bsum);
    cudaGetSymbolAddress((void**)&boff, g_boff);

    constexpr int SMEM_BIG = 2 * (10240 + 2 * 10240);   // 61440
    constexpr int SMEM_FC  = 2 * (10240 + 2 * 5120);    // 40960

    // one-time init (first call = correctness run, outside graph capture)
    static cudaStream_t s2 = nullptr;
    static cudaEvent_t evFork = nullptr, evJoin = nullptr;
    if (s2 == nullptr) {
        cudaStreamCreateWithFlags(&s2, cudaStreamNonBlocking);
        cudaEventCreateWithFlags(&evFork, cudaEventDisableTiming);
        cudaEventCreateWithFlags(&evJoin, cudaEventDisableTiming);
        cudaFuncSetAttribute((const void*)k_gemm_mma<128, 256, true>,
                             cudaFuncAttributeMaxDynamicSharedMemorySize, SMEM_BIG);
        cudaFuncSetAttribute((const void*)k_gemm_mma<64, 64, false>,
                             cudaFuncAttributeMaxDynamicSharedMemorySize, SMEM_FC);
    }

    const int NTILE = (NNODE + 127) / 128;   // 391
    dim3 gbig(NTILE, 2);
    dim3 gfc(NTILE, 1);

    // fork side stream
    cudaEventRecord(evFork, 0);
    cudaStreamWaitEvent(s2, evFork, 0);

    // main stream: convert x + split W1, then GEMM1
    k_cvt_x<<<(NNODE * FDIM / 4 + 255) / 256, 256>>>(
        (const float4*)x, (__half2*)xh);
    k_split_w_f16<<<(FDIM * FDIM + 255) / 256, 256>>>(W1, w1h, w1l, FDIM, FDIM);

    // side stream: CSR build + W2/fc splits
    cudaMemsetAsync(deg, 0, NNODE * sizeof(int), s2);
    k_count_deg<<<(NEDGE + 255) / 256, 256, 0, s2>>>(ei, deg);
    k_scan1<<<NBLK, 1024, 0, s2>>>(deg, rowptr, bsum);
    k_scan2<<<1, 32, 0, s2>>>(bsum, boff, rowptr);
    k_scan3<<<NBLK, 1024, 0, s2>>>(rowptr, cursor, boff);
    k_scatter<<<(EPAD + 255) / 256, 256, 0, s2>>>(ei, cursor, srcs);
    k_split_w_f16<<<(FDIM * FDIM + 255) / 256, 256, 0, s2>>>(W2, w2h, w2l, FDIM, FDIM);
    k_split_w_f16<<<(FDIM * OUTD + 255) / 256, 256, 0, s2>>>(fcW, wfh, wfl, FDIM, OUTD);
    cudaEventRecord(evJoin, s2);

    // layer-1 GEMM (fp16 2-term, fused logits)
    k_gemm_mma<128, 256, true><<<gbig, 256, SMEM_BIG>>>(
        (const uint16_t*)xh, w1h, w1l, nullptr, t, NNODE,
        asrc1, adst1, als, ald);

    // join: aggregation needs CSR; layer-2 GEMM needs W2 split
    cudaStreamWaitEvent(0, evJoin, 0);

    // layer 1 aggregate -> h1 (fp16)
    k_gat_aggregate<<<NNODE, 128>>>((const __half2*)t, rowptr, srcs, als, ald,
                                    b1, (__half2*)h1);

    // layer 2 (fp16 2-term)
    k_gemm_mma<128, 256, true><<<gbig, 256, SMEM_BIG>>>(
        (const uint16_t*)h1, w2h, w2l, nullptr, t, NNODE,
        asrc2, adst2, als, ald);
    k_gat_aggregate<<<NNODE, 128>>>((const __half2*)t, rowptr, srcs, als, ald,
                                    b2, (__half2*)h2);

    // fc head (fp16 2-term, fp32 out + bias)
    k_gemm_mma<64, 64, false><<<gfc, 256, SMEM_FC>>>(
        (const uint16_t*)h2, wfh, wfl, fcb, out, NNODE,
        nullptr, nullptr, nullptr, nullptr);
}

// round 16
// speedup vs baseline: 1.2618x; 1.0185x over previous
#include <cuda_runtime.h>
#include <cuda_fp16.h>
#include <math.h>
#include <stdint.h>

#define NNODE 50000
#define NEDGE 800000
#define EPAD  (NEDGE + NNODE)
#define FDIM  256
#define NHEAD 4
#define OUTD  64
#define NBLK  ((NNODE + 1023) / 1024)   // 49 scan blocks
#define NT_A  196                        // chunk A tiles (rows 0..25088)
#define NODE_A (NT_A * 128)              // 25088
#define NT_B  195                        // chunk B tiles
#define NODE_B (NNODE - NODE_A)          // 24912

// ---------------- scratch ---------------------------------------------------
__device__ __align__(128) __half g_t[NNODE * FDIM];       // GEMM out, fp16 msgs
__device__ __align__(16) __half g_h1[NNODE * FDIM];       // layer-1 h, fp16
__device__ __align__(16) __half g_h2[NNODE * FDIM];       // layer-2 h, fp16
__device__ __align__(16) uint16_t g_w1h[FDIM * FDIM];     // W1^T hi fp16 [N][K]
__device__ __align__(16) uint16_t g_w1l[FDIM * FDIM];
__device__ __align__(16) uint16_t g_w2h[FDIM * FDIM];
__device__ __align__(16) uint16_t g_w2l[FDIM * FDIM];
__device__ __align__(16) uint16_t g_wfh[OUTD * FDIM];
__device__ __align__(16) uint16_t g_wfl[OUTD * FDIM];
__device__ float g_als[NNODE * NHEAD];
__device__ float g_ald[NNODE * NHEAD];
__device__ int   g_deg[NNODE];
__device__ int   g_rowptr[NNODE + 1];
__device__ int   g_cursor[NNODE];
__device__ int   g_srcs[EPAD];
__device__ int   g_bsum[NBLK + 1];
__device__ int   g_boff[NBLK + 1];

__device__ __forceinline__ int clampi(int v, int lo, int hi) {
    return v < lo ? lo : (v > hi ? hi : v);
}
__device__ __forceinline__ void mma_f16(float* d, const uint32_t* a, const uint32_t* b) {
    asm volatile(
        "mma.sync.aligned.m16n8k16.row.col.f32.f16.f16.f32 "
        "{%0,%1,%2,%3}, {%4,%5,%6,%7}, {%8,%9}, {%0,%1,%2,%3};"
        : "+f"(d[0]), "+f"(d[1]), "+f"(d[2]), "+f"(d[3])
        : "r"(a[0]), "r"(a[1]), "r"(a[2]), "r"(a[3]), "r"(b[0]), "r"(b[1]));
}
#define LDSM_X4(r, addr)                                                     \
    asm volatile("ldmatrix.sync.aligned.m8n8.x4.shared.b16 {%0,%1,%2,%3}, [%4];" \
        : "=r"((r)[0]), "=r"((r)[1]), "=r"((r)[2]), "=r"((r)[3]) : "r"(addr))
#define CP_A16(dst, src, sz)                                                 \
    asm volatile("cp.async.cg.shared.global [%0], [%1], 16, %2;"             \
        :: "r"(dst), "l"(src), "r"(sz))
#define CP_COMMIT() asm volatile("cp.async.commit_group;" ::: "memory")
#define CP_WAIT0()  asm volatile("cp.async.wait_group 0;" ::: "memory")

// ---------------- CSR construction ------------------------------------------
__global__ void k_count_deg(const int* __restrict__ ei, int* deg) {
    int e = blockIdx.x * blockDim.x + threadIdx.x;
    if (e < NEDGE) atomicAdd(&deg[clampi(ei[NEDGE + e], 0, NNODE - 1)], 1);
}
__global__ void k_scan1(const int* __restrict__ deg, int* rowptr, int* bsum) {
    int b = blockIdx.x, tid = threadIdx.x;
    int i = b * 1024 + tid;
    int v = (i < NNODE) ? (deg[i] + 1) : 0;   // +1 self loop
    int lane = tid & 31, w = tid >> 5;
    int x = v;
#pragma unroll
    for (int off = 1; off < 32; off <<= 1) {
        int y = __shfl_up_sync(0xffffffffu, x, off);
        if (lane >= off) x += y;
    }
    __shared__ int ws[32];
    if (lane == 31) ws[w] = x;
    __syncthreads();
    if (w == 0) {
        int s = ws[lane];
#pragma unroll
        for (int off = 1; off < 32; off <<= 1) {
            int y = __shfl_up_sync(0xffffffffu, s, off);
            if (lane >= off) s += y;
        }
        ws[lane] = s;
    }
    __syncthreads();
    int wo = (w > 0) ? ws[w - 1] : 0;
    int incl = x + wo;
    if (i < NNODE) rowptr[i] = incl - v;
    if (tid == 1023) bsum[b] = incl;
}
__global__ void k_scan2(const int* __restrict__ bsum, int* boff, int* rowptr) {
    if (threadIdx.x == 0) {
        int s = 0;
        for (int b = 0; b < NBLK; b++) { boff[b] = s; s += bsum[b]; }
        rowptr[NNODE] = s;
    }
}
__global__ void k_scan3(int* rowptr, int* cursor, const int* __restrict__ boff) {
    int i = blockIdx.x * blockDim.x + threadIdx.x;
    if (i < NNODE) {
        int r = rowptr[i] + boff[i >> 10];
        rowptr[i] = r;
        cursor[i] = r;
    }
}
__global__ void k_scatter(const int* __restrict__ ei, int* cursor, int* srcs) {
    int e = blockIdx.x * blockDim.x + threadIdx.x;
    if (e < NEDGE) {
        int s = clampi(ei[e], 0, NNODE - 1);
        int d = clampi(ei[NEDGE + e], 0, NNODE - 1);
        int pos = atomicAdd(&cursor[d], 1);
        if (pos >= 0 && pos < EPAD) srcs[pos] = s;
    } else if (e < EPAD) {
        int i = e - NEDGE;
        int pos = atomicAdd(&cursor[i], 1);
        if (pos >= 0 && pos < EPAD) srcs[pos] = i;
    }
}

// ---------------- W[K][N] -> fp16 hi/lo [N][K] -------------------------------
__global__ void k_split_w_f16(const float* __restrict__ W, uint16_t* __restrict__ WH,
                              uint16_t* __restrict__ WL, int K, int N) {
    int i = blockIdx.x * blockDim.x + threadIdx.x;
    if (i < K * N) {
        int k = i / N, n = i % N;
        float v = W[i];
        __half h = __float2half_rn(v);
        __half l = __float2half_rn(v - __half2float(h));
        WH[n * K + k] = __half_as_ushort(h);
        WL[n * K + k] = __half_as_ushort(l);
    }
}

// ---------------- fp16 2-term tensor-core GEMM + fused logits ---------------
// CVT_A: A is fp32, converted to fp16 during register->smem staging.
// else:  A is fp16, loaded via cp.async.
// B fp16 hi/lo [NOUT][256] K-major. 2 MMAs/tile. row0 = row offset (chunking).
template<int BN, int NOUT, bool CVT_A, bool HALF_C>
__global__ void __launch_bounds__(256, 2)
k_gemm_mma(const void* __restrict__ Aptr,
           const uint16_t* __restrict__ BH, const uint16_t* __restrict__ BL,
           const float* __restrict__ bias, void* __restrict__ C, int M, int row0,
           const float* __restrict__ a_src, const float* __restrict__ a_dst,
           float* __restrict__ als_out, float* __restrict__ ald_out) {
    constexpr int RS = 40;                 // smem row stride (halves)
    constexpr int WN = BN / 2;
    constexpr int NT = WN / 8;
    constexpr int NP = NT / 2;
    constexpr int ABYTES = 128 * RS * 2;   // 10240
    constexpr int BBYTES = BN * RS * 2;
    constexpr int AOFF_H = 0;
    constexpr int BOFF_H = ABYTES;
    constexpr int BOFF_L = ABYTES + BBYTES;
    constexpr int STAGE  = ABYTES + 2 * BBYTES;
    constexpr int B_CH = BN / 64;          // 16B chunks/thread per B array

    extern __shared__ __align__(16) char smem[];
    const uint32_t sb = (uint32_t)__cvta_generic_to_shared(smem);

    const int tid  = threadIdx.x;
    const int wid  = tid >> 5, lane = tid & 31;
    const int wm   = wid & 3, wn = wid >> 2;
    const int g    = lane >> 2, tq = lane & 3;
    const int brow = row0 + blockIdx.x * 128;
    const int bcol = blockIdx.y * BN;

    float acc[2][NT][4];
#pragma unroll
    for (int mt = 0; mt < 2; mt++)
#pragma unroll
        for (int nt = 0; nt < NT; nt++)
#pragma unroll
            for (int r = 0; r < 4; r++) acc[mt][nt][r] = 0.f;

    const int lane8 = lane & 7, lh = (lane >> 3) & 1, lq = lane >> 4;
    uint32_t aOff[2], bOff[NP];
#pragma unroll
    for (int mt = 0; mt < 2; mt++) {
        int ar = wm * 32 + mt * 16 + lane8 + lh * 8;
        aOff[mt] = (uint32_t)(ar * RS + lq * 8) * 2;
    }
#pragma unroll
    for (int p = 0; p < NP; p++) {
        int br = wn * WN + p * 16 + lane8 + lq * 8;
        bOff[p] = (uint32_t)(br * RS + lh * 8) * 2;
    }

    auto cpB = [&](int k0, int stage) {
        uint32_t sbase = sb + stage * STAGE;
#pragma unroll
        for (int u = 0; u < B_CH; u++) {
            int q = tid + u * 256;
            int row = q >> 2, c8 = q & 3;
            size_t gi = (size_t)(bcol + row) * 256 + k0 + c8 * 8;
            uint32_t d = sbase + (uint32_t)(row * (RS * 2) + c8 * 16);
            CP_A16(d + BOFF_H, BH + gi, 16);
            CP_A16(d + BOFF_L, BL + gi, 16);
        }
    };
    auto cpA = [&](int k0, int stage) {
        const uint16_t* AH = (const uint16_t*)Aptr;
        uint32_t sbase = sb + stage * STAGE;
#pragma unroll
        for (int u = 0; u < 2; u++) {
            int q = tid + u * 256;
            int row = q >> 2, c8 = q & 3;
            int gr = brow + row;
            int sz = (gr < M) ? 16 : 0;
            int grc = (gr < M) ? gr : 0;
            size_t gi = (size_t)grc * 256 + k0 + c8 * 8;
            uint32_t d = sbase + (uint32_t)(row * (RS * 2) + c8 * 16);
            CP_A16(d + AOFF_H, AH + gi, sz);
        }
    };

    // fp32->fp16 staging (CVT_A path)
    float4 aS[4];
    auto loadA = [&](int k0) {
        const float* A = (const float*)Aptr;
#pragma unroll
        for (int u = 0; u < 4; u++) {
            int q = tid + u * 256;
            int row = q >> 3, f4 = q & 7;
            int gr = brow + row;
            aS[u] = make_float4(0.f, 0.f, 0.f, 0.f);
            if (gr < M) aS[u] = *reinterpret_cast<const float4*>(&A[(size_t)gr * 256 + k0 + f4 * 4]);
        }
    };
    auto storeA = [&](int stage) {
        uint16_t* pA = reinterpret_cast<uint16_t*>(smem + stage * STAGE + AOFF_H);
#pragma unroll
        for (int u = 0; u < 4; u++) {
            int q = tid + u * 256;
            int row = q >> 3, f4 = q & 7;
            int idx = row * RS + f4 * 4;
            *reinterpret_cast<__half2*>(pA + idx)     = __floats2half2_rn(aS[u].x, aS[u].y);
            *reinterpret_cast<__half2*>(pA + idx + 2) = __floats2half2_rn(aS[u].z, aS[u].w);
        }
    };

    auto compute = [&](int stage) {
        uint32_t sbase = sb + stage * STAGE;
#pragma unroll
        for (int ks = 0; ks < 2; ks++) {
            const uint32_t kb = ks * 32;
            uint32_t ah[2][4];
            LDSM_X4(ah[0], sbase + AOFF_H + aOff[0] + kb);
            LDSM_X4(ah[1], sbase + AOFF_H + aOff[1] + kb);
#pragma unroll
            for (int p = 0; p < NP; p++) {
                uint32_t bh[4], bl[4];
                LDSM_X4(bh, sbase + BOFF_H + bOff[p] + kb);
                LDSM_X4(bl, sbase + BOFF_L + bOff[p] + kb);
#pragma unroll
                for (int mt = 0; mt < 2; mt++) {
                    mma_f16(acc[mt][2 * p],     ah[mt], bh);
                    mma_f16(acc[mt][2 * p],     ah[mt], bl);
                    mma_f16(acc[mt][2 * p + 1], ah[mt], bh + 2);
                    mma_f16(acc[mt][2 * p + 1], ah[mt], bl + 2);
                }
            }
        }
    };

    if (CVT_A) {
        cpB(0, 0); CP_COMMIT();
        loadA(0); storeA(0);
        CP_WAIT0(); __syncthreads();
        int buf = 0;
        for (int t = 0; t < 8; t++) {
            if (t < 7) { cpB((t + 1) * 32, buf ^ 1); CP_COMMIT(); loadA((t + 1) * 32); }
            compute(buf);
            if (t < 7) { storeA(buf ^ 1); CP_WAIT0(); __syncthreads(); buf ^= 1; }
        }
    } else {
        cpA(0, 0); cpB(0, 0); CP_COMMIT();
        CP_WAIT0(); __syncthreads();
        int buf = 0;
        for (int t = 0; t < 8; t++) {
            if (t < 7) { cpA((t + 1) * 32, buf ^ 1); cpB((t + 1) * 32, buf ^ 1); CP_COMMIT(); }
            compute(buf);
            if (t < 7) { CP_WAIT0(); __syncthreads(); buf ^= 1; }
        }
    }

    // epilogue
#pragma unroll
    for (int mt = 0; mt < 2; mt++) {
        int r0 = brow + wm * 32 + mt * 16 + g;
        int r1 = r0 + 8;
#pragma unroll
        for (int nt = 0; nt < NT; nt++) {
            int col = bcol + wn * WN + nt * 8 + tq * 2;
            if (HALF_C) {
                __half2* Ch = reinterpret_cast<__half2*>(C);
                if (r0 < M)
                    Ch[(size_t)r0 * (NOUT / 2) + col / 2] =
                        __floats2half2_rn(acc[mt][nt][0], acc[mt][nt][1]);
                if (r1 < M)
                    Ch[(size_t)r1 * (NOUT / 2) + col / 2] =
                        __floats2half2_rn(acc[mt][nt][2], acc[mt][nt][3]);
            } else {
                float* Cf = reinterpret_cast<float*>(C);
                float b0 = 0.f, b1 = 0.f;
                if (bias) { b0 = bias[col]; b1 = bias[col + 1]; }
                if (r0 < M)
                    *reinterpret_cast<float2*>(&Cf[(size_t)r0 * NOUT + col]) =
                        make_float2(acc[mt][nt][0] + b0, acc[mt][nt][1] + b1);
                if (r1 < M)
                    *reinterpret_cast<float2*>(&Cf[(size_t)r1 * NOUT + col]) =
                        make_float2(acc[mt][nt][2] + b0, acc[mt][nt][3] + b1);
            }
        }
    }

    // fused attention logits (BN==128): head = blockIdx.y*2 + wn (fp32 acc)
    if (als_out) {
        int head = blockIdx.y * 2 + wn;
#pragma unroll
        for (int mt = 0; mt < 2; mt++) {
#pragma unroll
            for (int half = 0; half < 2; half++) {
                float ps = 0.f, pd = 0.f;
#pragma unroll
                for (int nt = 0; nt < NT; nt++) {
                    int col = bcol + wn * WN + nt * 8 + tq * 2;
                    float a0 = acc[mt][nt][half * 2 + 0];
                    float a1 = acc[mt][nt][half * 2 + 1];
                    ps += a0 * a_src[col] + a1 * a_src[col + 1];
                    pd += a0 * a_dst[col] + a1 * a_dst[col + 1];
                }
                ps += __shfl_xor_sync(0xffffffffu, ps, 1);
                pd += __shfl_xor_sync(0xffffffffu, pd, 1);
                ps += __shfl_xor_sync(0xffffffffu, ps, 2);
                pd += __shfl_xor_sync(0xffffffffu, pd, 2);
                int row = brow + wm * 32 + mt * 16 + g + half * 8;
                if (tq == 0 && row < M) {
                    als_out[row * NHEAD + head] = ps;
                    ald_out[row * NHEAD + head] = pd;
                }
            }
        }
    }
}

// ---------------- warp-synchronous aggregation (fp16 msgs, fp16 out) --------
// One node per 128-thread block (node = n0 + blockIdx.x); warp w owns head w.
// 2 edges per inner step with independent accumulator pairs.
__global__ void __launch_bounds__(128)
k_gat_aggregate(const __half2* __restrict__ hsrc,
                const int* __restrict__ rowptr,
                const int* __restrict__ srcs,
                const float* __restrict__ als,
                const float* __restrict__ ald,
                const float* __restrict__ bias,
                __half2* __restrict__ outv, int n0) {
    int n = n0 + blockIdx.x;
    int w = threadIdx.x >> 5;    // head == warp
    int lane = threadIdx.x & 31;
    int c2 = w * 32 + lane;

    int p0  = rowptr[n];
    int deg = rowptr[n + 1] - p0;

    float aldv = __ldg(&ald[n * NHEAD + w]);
    float ax0 = 0.f, ay0 = 0.f, ax1 = 0.f, ay1 = 0.f, dsum = 0.f;

    for (int base = 0; base < deg; base += 32) {
        int j = base + lane;
        int s = 0;
        float wt = 0.f;
        if (j < deg) {
            s = srcs[p0 + j];
            float e = als[s * NHEAD + w] + aldv;
            e = (e > 0.f) ? e : 0.2f * e;
            wt = __expf(e);
            dsum += wt;
        }
        int lim = min(32, deg - base);
        int j2 = 0;
#pragma unroll 2
        for (; j2 + 1 < lim; j2 += 2) {
            int   s0 = __shfl_sync(0xffffffffu, s,  j2);
            float w0 = __shfl_sync(0xffffffffu, wt, j2);
            int   s1 = __shfl_sync(0xffffffffu, s,  j2 + 1);
            float w1 = __shfl_sync(0xffffffffu, wt, j2 + 1);
            float2 v0 = __half22float2(hsrc[(size_t)s0 * 128 + c2]);
            float2 v1 = __half22float2(hsrc[(size_t)s1 * 128 + c2]);
            ax0 += w0 * v0.x; ay0 += w0 * v0.y;
            ax1 += w1 * v1.x; ay1 += w1 * v1.y;
        }
        if (j2 < lim) {
            int   s0 = __shfl_sync(0xffffffffu, s,  j2);
            float w0 = __shfl_sync(0xffffffffu, wt, j2);
            float2 v0 = __half22float2(hsrc[(size_t)s0 * 128 + c2]);
            ax0 += w0 * v0.x; ay0 += w0 * v0.y;
        }
    }

    float accx = ax0 + ax1, accy = ay0 + ay1;
#pragma unroll
    for (int off = 16; off >= 1; off >>= 1)
        dsum += __shfl_xor_sync(0xffffffffu, dsum, off);

    float inv = 1.f / dsum;
    float o0 = accx * inv + bias[2 * c2];
    float o1 = accy * inv + bias[2 * c2 + 1];
    o0 = (o0 > 0.f) ? o0 : expm1f(o0);
    o1 = (o1 > 0.f) ? o1 : expm1f(o1);

    outv[(size_t)n * 128 + c2] = __floats2half2_rn(o0, o1);
}

// ---------------- launch ----------------------------------------------------
extern "C" void kernel_launch(void* const* d_in, const int* in_sizes, int n_in,
                              void* d_out, int out_size) {
    const float* x     = (const float*)d_in[0];
    const int*   ei    = (const int*)d_in[1];   // int32 (JAX x64 disabled)
    const float* W1    = (const float*)d_in[3];
    const float* asrc1 = (const float*)d_in[4];
    const float* adst1 = (const float*)d_in[5];
    const float* b1    = (const float*)d_in[6];
    const float* W2    = (const float*)d_in[7];
    const float* asrc2 = (const float*)d_in[8];
    const float* adst2 = (const float*)d_in[9];
    const float* b2    = (const float*)d_in[10];
    const float* fcW   = (const float*)d_in[11];
    const float* fcb   = (const float*)d_in[12];
    float* out = (float*)d_out;

    __half *t, *h1, *h2;
    float *als, *ald;
    uint16_t *w1h, *w1l, *w2h, *w2l, *wfh, *wfl;
    int *deg, *rowptr, *cursor, *srcs, *bsum, *boff;
    cudaGetSymbolAddress((void**)&t, g_t);
    cudaGetSymbolAddress((void**)&h1, g_h1);
    cudaGetSymbolAddress((void**)&h2, g_h2);
    cudaGetSymbolAddress((void**)&als, g_als);
    cudaGetSymbolAddress((void**)&ald, g_ald);
    cudaGetSymbolAddress((void**)&w1h, g_w1h);
    cudaGetSymbolAddress((void**)&w1l, g_w1l);
    cudaGetSymbolAddress((void**)&w2h, g_w2h);
    cudaGetSymbolAddress((void**)&w2l, g_w2l);
    cudaGetSymbolAddress((void**)&wfh, g_wfh);
    cudaGetSymbolAddress((void**)&wfl, g_wfl);
    cudaGetSymbolAddress((void**)&deg, g_deg);
    cudaGetSymbolAddress((void**)&rowptr, g_rowptr);
    cudaGetSymbolAddress((void**)&cursor, g_cursor);
    cudaGetSymbolAddress((void**)&srcs, g_srcs);
    cudaGetSymbolAddress((void**)&bsum, g_bsum);
    cudaGetSymbolAddress((void**)&boff, g_boff);

    constexpr int SMEM_BIG = 2 * (10240 + 2 * 10240);   // 61440
    constexpr int SMEM_FC  = 2 * (10240 + 2 * 5120);    // 40960

    // one-time init (first call = correctness run, outside graph capture)
    static cudaStream_t s2 = nullptr;
    static cudaEvent_t evFork = nullptr, evJoin = nullptr;
    static cudaEvent_t evAgg1A = nullptr, evG2A = nullptr;
    static cudaEvent_t evAgg2A = nullptr, evFcA = nullptr;
    if (s2 == nullptr) {
        cudaStreamCreateWithFlags(&s2, cudaStreamNonBlocking);
        cudaEventCreateWithFlags(&evFork, cudaEventDisableTiming);
        cudaEventCreateWithFlags(&evJoin, cudaEventDisableTiming);
        cudaEventCreateWithFlags(&evAgg1A, cudaEventDisableTiming);
        cudaEventCreateWithFlags(&evG2A, cudaEventDisableTiming);
        cudaEventCreateWithFlags(&evAgg2A, cudaEventDisableTiming);
        cudaEventCreateWithFlags(&evFcA, cudaEventDisableTiming);
        cudaFuncSetAttribute((const void*)k_gemm_mma<128, 256, true, true>,
                             cudaFuncAttributeMaxDynamicSharedMemorySize, SMEM_BIG);
        cudaFuncSetAttribute((const void*)k_gemm_mma<128, 256, false, true>,
                             cudaFuncAttributeMaxDynamicSharedMemorySize, SMEM_BIG);
        cudaFuncSetAttribute((const void*)k_gemm_mma<64, 64, false, false>,
                             cudaFuncAttributeMaxDynamicSharedMemorySize, SMEM_FC);
    }

    // fork side stream: CSR build + W2/fc splits
    cudaEventRecord(evFork, 0);
    cudaStreamWaitEvent(s2, evFork, 0);
    cudaMemsetAsync(deg, 0, NNODE * sizeof(int), s2);
    k_count_deg<<<(NEDGE + 255) / 256, 256, 0, s2>>>(ei, deg);
    k_scan1<<<NBLK, 1024, 0, s2>>>(deg, rowptr, bsum);
    k_scan2<<<1, 32, 0, s2>>>(bsum, boff, rowptr);
    k_scan3<<<NBLK, 1024, 0, s2>>>(rowptr, cursor, boff);
    k_scatter<<<(EPAD + 255) / 256, 256, 0, s2>>>(ei, cursor, srcs);
    k_split_w_f16<<<(FDIM * FDIM + 255) / 256, 256, 0, s2>>>(W2, w2h, w2l, FDIM, FDIM);
    k_split_w_f16<<<(FDIM * OUTD + 255) / 256, 256, 0, s2>>>(fcW, wfh, wfl, FDIM, OUTD);
    cudaEventRecord(evJoin, s2);

    // main: split W1 then layer-1 GEMM (CVT_A: fp32 x converted in-kernel)
    k_split_w_f16<<<(FDIM * FDIM + 255) / 256, 256>>>(W1, w1h, w1l, FDIM, FDIM);
    dim3 gbig((NNODE + 127) / 128, 2);   // (391, 2)
    k_gemm_mma<128, 256, true, true><<<gbig, 256, SMEM_BIG>>>(
        x, w1h, w1l, nullptr, t, NNODE, 0, asrc1, adst1, als, ald);

    // join: aggregation needs CSR
    cudaStreamWaitEvent(0, evJoin, 0);

    // ---- chunked pipeline: agg1_A -> (agg1_B || GEMM2_A) -> GEMM2_B ... ----
    k_gat_aggregate<<<NODE_A, 128>>>((const __half2*)t, rowptr, srcs, als, ald,
                                     b1, (__half2*)h1, 0);
    cudaEventRecord(evAgg1A, 0);
    k_gat_aggregate<<<NODE_B, 128>>>((const __half2*)t, rowptr, srcs, als, ald,
                                     b1, (__half2*)h1, NODE_A);

    // GEMM2 chunk A on side stream (needs h1 rows [0, NODE_A) only)
    cudaStreamWaitEvent(s2, evAgg1A, 0);
    k_gemm_mma<128, 256, false, true><<<dim3(NT_A, 2), 256, SMEM_BIG, s2>>>(
        (const uint16_t*)h1, w2h, w2l, nullptr, t, NNODE, 0,
        asrc2, adst2, als, ald);
    cudaEventRecord(evG2A, s2);

    // GEMM2 chunk B on main (after agg1_B by program order)
    k_gemm_mma<128, 256, false, true><<<dim3(NT_B, 2), 256, SMEM_BIG>>>(
        (const uint16_t*)h1, w2h, w2l, nullptr, t, NNODE, NODE_A,
        asrc2, adst2, als, ald);

    // agg2 needs ALL of t (GEMM2 A + B)
    cudaStreamWaitEvent(0, evG2A, 0);
    k_gat_aggregate<<<NODE_A, 128>>>((const __half2*)t, rowptr, srcs, als, ald,
                                     b2, (__half2*)h2, 0);
    cudaEventRecord(evAgg2A, 0);
    k_gat_aggregate<<<NODE_B, 128>>>((const __half2*)t, rowptr, srcs, als, ald,
                                     b2, (__half2*)h2, NODE_A);

    // fc chunk A on side stream (needs h2 rows [0, NODE_A) only)
    cudaStreamWaitEvent(s2, evAgg2A, 0);
    k_gemm_mma<64, 64, false, false><<<dim3(NT_A, 1), 256, SMEM_FC, s2>>>(
        (const uint16_t*)h2, wfh, wfl, fcb, out, NNODE, 0,
        nullptr, nullptr, nullptr, nullptr);
    cudaEventRecord(evFcA, s2);

    // fc chunk B on main (after agg2_B by program order)
    k_gemm_mma<64, 64, false, false><<<dim3(NT_B, 1), 256, SMEM_FC>>>(
        (const uint16_t*)h2, wfh, wfl, fcb, out, NNODE, NODE_A,
        nullptr, nullptr, nullptr, nullptr);

    // final join
    cudaStreamWaitEvent(0, evFcA, 0);
}